// round 12
// baseline (speedup 1.0000x reference)
#include <cuda_runtime.h>
#include <cuda_fp16.h>
#include <math.h>
#include <stdint.h>

#define DDIM   2048
#define NEXP   64
#define NCOL   128            // router(64) | noise(64) output columns
#define TM     64             // tokens per CTA
#define KC     32             // K elems per tensor ring chunk
#define NC_T   52             // tensor chunks -> K_t = 1664
#define KOFF   1664
#define NF     6              // fp32 tail chunks of 64 -> K_f = 384
#define NTHREADS 256          // w0-3 consumers, w4-5 producers, w6-7 ffma
#define NPROD  64
#define NCONS  128
#define AS     133
#define US     65
#define WSCALE 2048.0f
#define INVSCALE (1.0f / 2048.0f)

#define RSTRIDE 80                     // ring row stride bytes (64B data + 16 pad)
#define A_PL    (TM  * RSTRIDE)        // 5120
#define B_PL    (NCOL * RSTRIDE)       // 10240
#define STAGE_A (2 * A_PL)             // 10240
#define STAGE_BYTES (STAGE_A + 2 * B_PL)   // 30720
#define SM_RING 64
#define SM_TAILX (SM_RING + 2 * STAGE_BYTES)   // 61504
#define XT_S    68                      // xT row stride (floats), 16B-aligned rows
#define WT_S    132                     // wT row stride (floats), 16B-aligned rows
#define SM_TAILW (SM_TAILX + 64 * XT_S * 4)    // 78912
#define SMEM_BYTES (SM_TAILW + 64 * WT_S * 4)  // 112704 (x2 CTAs/SM = 225408)

// pre-split W fp16 planes, scaled by 2048 (router rows 0..63, noise rows 64..127)
__device__ __half g_wp[2][NCOL][DDIM];

// ---------------- helpers ----------------
__device__ __forceinline__ uint32_t smem_u32(const void* p) {
    uint32_t a;
    asm("{ .reg .u64 t; cvta.to.shared.u64 t, %1; cvt.u32.u64 %0, t; }" : "=r"(a) : "l"(p));
    return a;
}
__device__ __forceinline__ void mbar_init(uint32_t a, uint32_t cnt) {
    asm volatile("mbarrier.init.shared.b64 [%0], %1;" :: "r"(a), "r"(cnt) : "memory");
}
__device__ __forceinline__ void mbar_arrive(uint32_t a) {
    asm volatile("mbarrier.arrive.shared.b64 _, [%0];" :: "r"(a) : "memory");
}
__device__ __forceinline__ void mbar_wait(uint32_t a, uint32_t parity) {
    asm volatile(
        "{\n\t.reg .pred P1;\n\t"
        "W%=:\n\t"
        "mbarrier.try_wait.parity.acquire.cta.shared::cta.b64 P1, [%0], %1, 0x989680;\n\t"
        "@P1 bra.uni D%=;\n\t"
        "bra.uni W%=;\n\t"
        "D%=:\n\t}"
        :: "r"(a), "r"(parity) : "memory");
}
__device__ __forceinline__ void split2(float lo, float hi, uint32_t& u0, uint32_t& u1) {
    __half2 h0 = __floats2half2_rn(lo, hi);
    float l0 = __half2float(__low2half(h0));
    float hh = __half2float(__high2half(h0));
    __half2 h1 = __floats2half2_rn(lo - l0, hi - hh);
    u0 = *reinterpret_cast<uint32_t*>(&h0);
    u1 = *reinterpret_cast<uint32_t*>(&h1);
}
#define LDSM4(r, a) \
    asm volatile("ldmatrix.sync.aligned.m8n8.x4.shared.b16 {%0,%1,%2,%3}, [%4];" \
        : "=r"((r)[0]), "=r"((r)[1]), "=r"((r)[2]), "=r"((r)[3]) : "r"(a))
#define MMA16816(d, a, b) \
    asm volatile("mma.sync.aligned.m16n8k16.row.col.f32.f16.f16.f32 " \
        "{%0,%1,%2,%3}, {%4,%5,%6,%7}, {%8,%9}, {%0,%1,%2,%3};" \
        : "+f"((d)[0]), "+f"((d)[1]), "+f"((d)[2]), "+f"((d)[3]) \
        : "r"((a)[0]), "r"((a)[1]), "r"((a)[2]), "r"((a)[3]), "r"((b)[0]), "r"((b)[1]))
#define CPASYNC16(dst, src) \
    asm volatile("cp.async.cg.shared.global [%0], [%1], 16;" :: "r"(dst), "l"(src) : "memory")

// ---------------- prep: split W into 2 scaled fp16 planes ----------------
__global__ void prep_w_kernel(const float* __restrict__ rw, const float* __restrict__ nw) {
    int idx = blockIdx.x * blockDim.x + threadIdx.x;
    int r = idx >> 11, k = idx & 2047;
    float v = WSCALE * ((r < NEXP) ? rw[r * DDIM + k] : nw[(r - NEXP) * DDIM + k]);
    __half b0 = __float2half_rn(v);
    __half b1 = __float2half_rn(v - __half2float(b0));
    g_wp[0][r][k] = b0;
    g_wp[1][r][k] = b1;
}

// ---------------- main fused kernel ----------------
extern __shared__ char smem[];

__global__ __launch_bounds__(NTHREADS, 2)
void router_hmma_kernel(const float* __restrict__ x,
                        const float* __restrict__ rw,
                        const float* __restrict__ rb,
                        const float* __restrict__ nw,
                        const float* __restrict__ nb,
                        const float* __restrict__ u,
                        float* __restrict__ out,
                        int M)
{
    const int tid  = threadIdx.x;
    const int wid  = tid >> 5;
    const int lane = tid & 31;
    const int m0   = blockIdx.x * TM;
    const uint32_t sb = smem_u32(smem);
    // mbars: ring full[s]=sb+s*16, empty[s]=sb+s*16+8; tail full=sb+32, empty=sb+40
    if (tid == 0) {
        mbar_init(sb + 0,  NPROD);  mbar_init(sb + 8,  NCONS);
        mbar_init(sb + 16, NPROD);  mbar_init(sb + 24, NCONS);
        mbar_init(sb + 32, NPROD);                 // tail full: 64 producer arrivals
        mbar_init(sb + 40, 2 * NPROD);             // tail empty: 128 aux arrivals
    }
    __syncthreads();

    float* acc_s = (float*)(smem + SM_RING);   // epilogue staging (overlaps dead ring)
    float* su    = acc_s + TM * AS;
    float* xt    = (float*)(smem + SM_TAILX);  // [64 k][XT_S] fp32 (token-major rows)
    float* wt    = (float*)(smem + SM_TAILW);  // [64 k][WT_S] fp32

    if (wid >= 4) {
        // ============ AUX: producers (w4-5) + ffma (w6-7) ============
        const bool is_prod = (wid < 6);
        const int  ptid = tid - NCONS;            // producers: 0..63
        const int  atid = tid - NCONS;            // aux tile id 0..127
        const int  tg = atid >> 3;                // 16 groups x 4 tokens
        const int  cg = atid & 7;                 // 8 groups x 16 cols
        float facc[4][16];
#pragma unroll
        for (int j = 0; j < 4; j++)
#pragma unroll
            for (int i = 0; i < 16; i++) facc[j][i] = 0.f;

        if (is_prod) {
            // -------- producer: ring staging + tail staging + tail ffma share ----
            for (int c = 0; c < NC_T; c++) {
                const int s = c & 1;
                const uint32_t aA = sb + SM_RING + s * STAGE_BYTES;
                const uint32_t aB = aA + STAGE_A;
                mbar_wait(sb + s * 16 + 8, ((c >> 1) & 1) ^ 1);   // ring empty

                // B: 2 planes x 128 rows x 4 cells(16B) = 1024 cells, 16/thread
#pragma unroll
                for (int i = 0; i < 16; i++) {
                    int q = ptid + i * NPROD;
                    int pl = q >> 9, rem = q & 511, row = rem >> 2, cgi = rem & 3;
                    uint32_t dst = aB + pl * B_PL + row * RSTRIDE + cgi * 16;
                    CPASYNC16(dst, &g_wp[pl][row][c * KC + cgi * 8]);
                }
                asm volatile("cp.async.commit_group;" ::: "memory");

                // A: 64 rows x 8 float4, 8/thread
                float4 av[8];
#pragma unroll
                for (int i = 0; i < 8; i++) {
                    int q = ptid + i * NPROD;
                    int row = q >> 3, kq = q & 7;
                    av[i] = *(const float4*)(x + (size_t)(m0 + row) * DDIM + c * KC + kq * 4);
                }
#pragma unroll
                for (int i = 0; i < 8; i++) {
                    int q = ptid + i * NPROD;
                    int row = q >> 3, kq = q & 7;
                    uint32_t p0a, p1a, p0b, p1b;
                    split2(av[i].x, av[i].y, p0a, p1a);
                    split2(av[i].z, av[i].w, p0b, p1b);
                    uint32_t base = (aA - sb) + row * RSTRIDE + kq * 8;
                    *(uint2*)(smem + base + 0 * A_PL) = make_uint2(p0a, p0b);
                    *(uint2*)(smem + base + 1 * A_PL) = make_uint2(p1a, p1b);
                }
                asm volatile("cp.async.wait_group 0;" ::: "memory");
                mbar_arrive(sb + s * 16);                          // ring full

                // tail staging at c = 1, 9, 17, 25, 33, 41
                if (c >= 1 && c <= 41 && ((c - 1) & 7) == 0) {
                    const int t = (c - 1) >> 3;
                    const int kb = KOFF + t * 64;
                    mbar_wait(sb + 40, (t & 1) ^ 1);               // tail empty
                    // x tail: 64 rows x 16 f4 -> transposed xt[k][tok]
#pragma unroll
                    for (int i = 0; i < 16; i++) {
                        int q = ptid + i * NPROD;
                        int row = q >> 4, kq = q & 15;
                        float4 v = *(const float4*)(x + (size_t)(m0 + row) * DDIM + kb + kq * 4);
                        xt[(kq * 4 + 0) * XT_S + row] = v.x;
                        xt[(kq * 4 + 1) * XT_S + row] = v.y;
                        xt[(kq * 4 + 2) * XT_S + row] = v.z;
                        xt[(kq * 4 + 3) * XT_S + row] = v.w;
                    }
                    // w tail: 128 rows x 16 f4 -> transposed wt[k][col]
#pragma unroll
                    for (int i = 0; i < 32; i++) {
                        int q = ptid + i * NPROD;
                        int row = q >> 4, kq = q & 15;
                        const float* wsrc = (row < NEXP)
                            ? (rw + (size_t)row * DDIM)
                            : (nw + (size_t)(row - NEXP) * DDIM);
                        float4 v = *(const float4*)(wsrc + kb + kq * 4);
                        wt[(kq * 4 + 0) * WT_S + row] = v.x;
                        wt[(kq * 4 + 1) * WT_S + row] = v.y;
                        wt[(kq * 4 + 2) * WT_S + row] = v.z;
                        wt[(kq * 4 + 3) * WT_S + row] = v.w;
                    }
                    mbar_arrive(sb + 32);                          // tail full
                }
                // producer's ffma share at c = 3, 11, 19, 27, 35, 43
                if (c >= 3 && c <= 43 && ((c - 3) & 7) == 0) {
                    const int t = (c - 3) >> 3;
                    mbar_wait(sb + 32, t & 1);                     // tail full
                    for (int k = 0; k < 64; k++) {
                        float4 xv = *(const float4*)(xt + k * XT_S + tg * 4);
#pragma unroll
                        for (int q4 = 0; q4 < 4; q4++) {
                            float4 wv = *(const float4*)(wt + k * WT_S + cg * 16 + q4 * 4);
                            facc[0][q4 * 4 + 0] += xv.x * wv.x;
                            facc[0][q4 * 4 + 1] += xv.x * wv.y;
                            facc[0][q4 * 4 + 2] += xv.x * wv.z;
                            facc[0][q4 * 4 + 3] += xv.x * wv.w;
                            facc[1][q4 * 4 + 0] += xv.y * wv.x;
                            facc[1][q4 * 4 + 1] += xv.y * wv.y;
                            facc[1][q4 * 4 + 2] += xv.y * wv.z;
                            facc[1][q4 * 4 + 3] += xv.y * wv.w;
                            facc[2][q4 * 4 + 0] += xv.z * wv.x;
                            facc[2][q4 * 4 + 1] += xv.z * wv.y;
                            facc[2][q4 * 4 + 2] += xv.z * wv.z;
                            facc[2][q4 * 4 + 3] += xv.z * wv.w;
                            facc[3][q4 * 4 + 0] += xv.w * wv.x;
                            facc[3][q4 * 4 + 1] += xv.w * wv.y;
                            facc[3][q4 * 4 + 2] += xv.w * wv.z;
                            facc[3][q4 * 4 + 3] += xv.w * wv.w;
                        }
                    }
                    mbar_arrive(sb + 40);                          // tail empty
                }
            }
        } else {
            // -------- dedicated ffma warps: consume all NF tail chunks ----------
            for (int t = 0; t < NF; t++) {
                mbar_wait(sb + 32, t & 1);                         // tail full
                for (int k = 0; k < 64; k++) {
                    float4 xv = *(const float4*)(xt + k * XT_S + tg * 4);
#pragma unroll
                    for (int q4 = 0; q4 < 4; q4++) {
                        float4 wv = *(const float4*)(wt + k * WT_S + cg * 16 + q4 * 4);
                        facc[0][q4 * 4 + 0] += xv.x * wv.x;
                        facc[0][q4 * 4 + 1] += xv.x * wv.y;
                        facc[0][q4 * 4 + 2] += xv.x * wv.z;
                        facc[0][q4 * 4 + 3] += xv.x * wv.w;
                        facc[1][q4 * 4 + 0] += xv.y * wv.x;
                        facc[1][q4 * 4 + 1] += xv.y * wv.y;
                        facc[1][q4 * 4 + 2] += xv.y * wv.z;
                        facc[1][q4 * 4 + 3] += xv.y * wv.w;
                        facc[2][q4 * 4 + 0] += xv.z * wv.x;
                        facc[2][q4 * 4 + 1] += xv.z * wv.y;
                        facc[2][q4 * 4 + 2] += xv.z * wv.z;
                        facc[2][q4 * 4 + 3] += xv.z * wv.w;
                        facc[3][q4 * 4 + 0] += xv.w * wv.x;
                        facc[3][q4 * 4 + 1] += xv.w * wv.y;
                        facc[3][q4 * 4 + 2] += xv.w * wv.z;
                        facc[3][q4 * 4 + 3] += xv.w * wv.w;
                    }
                }
                mbar_arrive(sb + 40);                              // tail empty
            }
        }
        __syncthreads();   // sync1: consumers done with ring
        __syncthreads();   // sync2: consumers staged acc_s
        // merge fp32 tail into acc_s (scaled to match tensor accumulators)
#pragma unroll
        for (int j = 0; j < 4; j++)
#pragma unroll
            for (int i = 0; i < 16; i++)
                acc_s[(tg * 4 + j) * AS + cg * 16 + i] += facc[j][i] * WSCALE;
    } else {
        // ================= CONSUMER (warps 0-3, 128 threads) =================
        const int wm = wid >> 1;   // 0..1 -> 32-row slab
        const int wn = wid & 1;    // 0..1 -> 64-col slab

        uint32_t aoff[2], boff[4];
#pragma unroll
        for (int mt = 0; mt < 2; mt++) {
            int row = wm * 32 + mt * 16 + (lane & 7) + 8 * ((lane >> 3) & 1);
            aoff[mt] = (uint32_t)(row * RSTRIDE + 16 * ((lane >> 4) & 1));
        }
#pragma unroll
        for (int ntp = 0; ntp < 4; ntp++) {
            int row = wn * 64 + ntp * 16 + ((lane >> 4) & 1) * 8 + (lane & 7);
            boff[ntp] = (uint32_t)(row * RSTRIDE + 16 * ((lane >> 3) & 1));
        }

        float acc[2][8][4];
#pragma unroll
        for (int mt = 0; mt < 2; mt++)
#pragma unroll
            for (int nt = 0; nt < 8; nt++)
#pragma unroll
                for (int e = 0; e < 4; e++) acc[mt][nt][e] = 0.f;

        for (int c = 0; c < NC_T; c++) {
            const int s = c & 1;
            const uint32_t aA = sb + SM_RING + s * STAGE_BYTES;
            const uint32_t aB = aA + STAGE_A;
            mbar_wait(sb + s * 16, (c >> 1) & 1);                  // ring full

#pragma unroll
            for (int ks = 0; ks < 2; ks++) {
                uint32_t a0[2][4], a1[2][4], b[8][2];
#pragma unroll
                for (int mt = 0; mt < 2; mt++) {
                    LDSM4(a0[mt], aA + 0 * A_PL + ks * 32 + aoff[mt]);
                    LDSM4(a1[mt], aA + 1 * A_PL + ks * 32 + aoff[mt]);
                }
#pragma unroll
                for (int ntp = 0; ntp < 4; ntp++) {
                    uint32_t t4[4];
                    LDSM4(t4, aB + 0 * B_PL + ks * 32 + boff[ntp]);
                    b[2 * ntp][0] = t4[0]; b[2 * ntp][1] = t4[1];
                    b[2 * ntp + 1][0] = t4[2]; b[2 * ntp + 1][1] = t4[3];
                }
                // q00 + q10 on plane-0 B
#pragma unroll
                for (int mt = 0; mt < 2; mt++)
#pragma unroll
                    for (int nt = 0; nt < 8; nt++)
                        MMA16816(acc[mt][nt], a0[mt], b[nt]);
#pragma unroll
                for (int mt = 0; mt < 2; mt++)
#pragma unroll
                    for (int nt = 0; nt < 8; nt++)
                        MMA16816(acc[mt][nt], a1[mt], b[nt]);
                // reload plane-1 B, q01
#pragma unroll
                for (int ntp = 0; ntp < 4; ntp++) {
                    uint32_t t4[4];
                    LDSM4(t4, aB + 1 * B_PL + ks * 32 + boff[ntp]);
                    b[2 * ntp][0] = t4[0]; b[2 * ntp][1] = t4[1];
                    b[2 * ntp + 1][0] = t4[2]; b[2 * ntp + 1][1] = t4[3];
                }
#pragma unroll
                for (int mt = 0; mt < 2; mt++)
#pragma unroll
                    for (int nt = 0; nt < 8; nt++)
                        MMA16816(acc[mt][nt], a0[mt], b[nt]);
            }
            mbar_arrive(sb + s * 16 + 8);                          // ring empty
        }

        __syncthreads();   // sync1
#pragma unroll
        for (int mt = 0; mt < 2; mt++)
#pragma unroll
            for (int nt = 0; nt < 8; nt++) {
                int r   = wm * 32 + mt * 16 + (lane >> 2);
                int col = wn * 64 + nt * 8 + (lane & 3) * 2;
                acc_s[r * AS + col]           = acc[mt][nt][0];
                acc_s[r * AS + col + 1]       = acc[mt][nt][1];
                acc_s[(r + 8) * AS + col]     = acc[mt][nt][2];
                acc_s[(r + 8) * AS + col + 1] = acc[mt][nt][3];
            }
        __syncthreads();   // sync2
    }
    __syncthreads();       // sync3: tail merged, acc_s final

    // ---- noise_u tile (all threads) ----
    {
        const float* ug = u + (size_t)m0 * NEXP;
        for (int q = tid; q < TM * NEXP; q += NTHREADS) {
            int r = q >> 6, cn = q & 63;
            su[r * US + cn] = ug[(size_t)r * NEXP + cn];
        }
    }
    __syncthreads();

    // ---- per-token epilogue ----
    if (tid < TM) {
        const int m = m0 + tid;
        float* row = acc_s + tid * AS;
        const float* urow = su + tid * US;

        float v1 = -INFINITY, v2 = -INFINITY;
        int i1 = 0, i2 = 0;
        for (int e = 0; e < NEXP; e++) {
            float lg = row[e] * INVSCALE + rb[e];
            float nz = row[NEXP + e] * INVSCALE + nb[e];
            float sp = fmaxf(nz, 0.f) + log1pf(expf(-fabsf(nz)));
            float nv = lg + sp * urow[e];
            if (nv > v1) { v2 = v1; i2 = i1; v1 = nv; i1 = e; }
            else if (nv > v2) { v2 = nv; i2 = e; }
        }
        float e2 = expf(v2 - v1);
        float den = 1.f + e2;
        float p1 = 1.f / den;
        float p2 = e2 / den;

        for (int e = 0; e < NEXP; e++) row[e] = 0.f;
        row[i1] = p1;
        row[i2] = p2;

        float* oid = out + (size_t)M * NEXP;
        oid[(size_t)m * 2 + 0] = (float)i1;
        oid[(size_t)m * 2 + 1] = (float)i2;
    }
    __syncthreads();

    // coalesced probability writeback
    for (int t = tid; t < TM * (NEXP / 4); t += NTHREADS) {
        int r = t >> 4;
        int c4 = (t & 15) * 4;
        float4 v = make_float4(acc_s[r * AS + c4 + 0],
                               acc_s[r * AS + c4 + 1],
                               acc_s[r * AS + c4 + 2],
                               acc_s[r * AS + c4 + 3]);
        *(float4*)(out + (size_t)(m0 + r) * NEXP + c4) = v;
    }
}

extern "C" void kernel_launch(void* const* d_in, const int* in_sizes, int n_in,
                              void* d_out, int out_size)
{
    const float* x  = (const float*)d_in[0];
    const float* rw = (const float*)d_in[1];
    const float* rb = (const float*)d_in[2];
    const float* nw = (const float*)d_in[3];
    const float* nb = (const float*)d_in[4];
    const float* u  = (const float*)d_in[5];

    const int M = in_sizes[0] / DDIM;  // 16384

    static bool attr_set = false;
    if (!attr_set) {
        cudaFuncSetAttribute(router_hmma_kernel,
                             cudaFuncAttributeMaxDynamicSharedMemorySize,
                             SMEM_BYTES);
        attr_set = true;
    }

    prep_w_kernel<<<(NCOL * DDIM) / 256, 256>>>(rw, nw);
    router_hmma_kernel<<<M / TM, NTHREADS, SMEM_BYTES>>>(x, rw, rb, nw, nb, u,
                                                         (float*)d_out, M);
}

// round 13
// speedup vs baseline: 2.6795x; 2.6795x over previous
#include <cuda_runtime.h>
#include <cuda_fp16.h>
#include <math.h>
#include <stdint.h>

#define DDIM   2048
#define NEXP   64
#define NCOL   128            // router(64) | noise(64) output columns
#define TM     64             // tokens per CTA
#define KC     64             // K elems per chunk
#define NC     (DDIM / KC)    // 32 chunks
#define NTHREADS 192          // 4 consumer warps + 2 producer warps
#define NPROD  64
#define NCONS_THREADS 128
#define AS     133
#define US     65
#define WSCALE 2048.0f
#define INVSCALE (1.0f / 2048.0f)

#define RSTRIDE 144                    // smem row stride bytes (128B data + 16B pad)
#define A_PL    (TM  * RSTRIDE)        // 9216  B per A plane (64 rows)
#define B_PL    (NCOL * RSTRIDE)       // 18432 B per B plane (128 rows)
#define STAGE_A (2 * A_PL)             // 18432
#define STAGE_BYTES (STAGE_A + 2 * B_PL)   // 55296
#define STAGES  2
#define SM_RING 1024
#define SMEM_BYTES (SM_RING + STAGES * STAGE_BYTES)   // 111616 (x2 CTAs/SM)

// pre-split W planes, scaled by 2048 (router rows 0..63, noise rows 64..127)
__device__ __half g_wp[2][NCOL][DDIM];

// ---------------- helpers ----------------
__device__ __forceinline__ uint32_t smem_u32(const void* p) {
    uint32_t a;
    asm("{ .reg .u64 t; cvta.to.shared.u64 t, %1; cvt.u32.u64 %0, t; }" : "=r"(a) : "l"(p));
    return a;
}
__device__ __forceinline__ void mbar_init(uint32_t a, uint32_t cnt) {
    asm volatile("mbarrier.init.shared.b64 [%0], %1;" :: "r"(a), "r"(cnt) : "memory");
}
__device__ __forceinline__ void mbar_arrive(uint32_t a) {
    asm volatile("mbarrier.arrive.shared.b64 _, [%0];" :: "r"(a) : "memory");
}
__device__ __forceinline__ void mbar_wait(uint32_t a, uint32_t parity) {
    asm volatile(
        "{\n\t.reg .pred P1;\n\t"
        "W%=:\n\t"
        "mbarrier.try_wait.parity.acquire.cta.shared::cta.b64 P1, [%0], %1, 0x989680;\n\t"
        "@P1 bra.uni D%=;\n\t"
        "bra.uni W%=;\n\t"
        "D%=:\n\t}"
        :: "r"(a), "r"(parity) : "memory");
}
// 2-way fp16 split of a float pair (lo,hi) -> 2 f16x2 regs
__device__ __forceinline__ void split2(float lo, float hi, uint32_t& u0, uint32_t& u1) {
    __half2 h0 = __floats2half2_rn(lo, hi);
    float l0 = __half2float(__low2half(h0));
    float hh = __half2float(__high2half(h0));
    __half2 h1 = __floats2half2_rn(lo - l0, hi - hh);
    u0 = *reinterpret_cast<uint32_t*>(&h0);
    u1 = *reinterpret_cast<uint32_t*>(&h1);
}
#define LDSM4(r, a) \
    asm volatile("ldmatrix.sync.aligned.m8n8.x4.shared.b16 {%0,%1,%2,%3}, [%4];" \
        : "=r"((r)[0]), "=r"((r)[1]), "=r"((r)[2]), "=r"((r)[3]) : "r"(a))
#define MMA16816(d, a, b) \
    asm volatile("mma.sync.aligned.m16n8k16.row.col.f32.f16.f16.f32 " \
        "{%0,%1,%2,%3}, {%4,%5,%6,%7}, {%8,%9}, {%0,%1,%2,%3};" \
        : "+f"((d)[0]), "+f"((d)[1]), "+f"((d)[2]), "+f"((d)[3]) \
        : "r"((a)[0]), "r"((a)[1]), "r"((a)[2]), "r"((a)[3]), "r"((b)[0]), "r"((b)[1]))
#define CPASYNC16(dst, src) \
    asm volatile("cp.async.cg.shared.global [%0], [%1], 16;" :: "r"(dst), "l"(src) : "memory")

// ---------------- prep: split W into 2 scaled fp16 planes (vectorized) ----------------
// 4 elements per thread via float4: MLP=4, paired half2 stores. 65536 threads total.
__global__ void prep_w_kernel(const float* __restrict__ rw, const float* __restrict__ nw) {
    int idx = blockIdx.x * blockDim.x + threadIdx.x;      // 0 .. 65535
    int r  = idx >> 9;                                    // row 0..127
    int k4 = (idx & 511) * 4;                             // k offset, /4 aligned
    const float* src = (r < NEXP) ? (rw + (size_t)r * DDIM)
                                  : (nw + (size_t)(r - NEXP) * DDIM);
    float4 v = *(const float4*)(src + k4);
    v.x *= WSCALE; v.y *= WSCALE; v.z *= WSCALE; v.w *= WSCALE;

    __half2 p0a = __floats2half2_rn(v.x, v.y);
    __half2 p0b = __floats2half2_rn(v.z, v.w);
    float r0 = v.x - __half2float(__low2half(p0a));
    float r1 = v.y - __half2float(__high2half(p0a));
    float r2 = v.z - __half2float(__low2half(p0b));
    float r3 = v.w - __half2float(__high2half(p0b));
    __half2 p1a = __floats2half2_rn(r0, r1);
    __half2 p1b = __floats2half2_rn(r2, r3);

    *(__half2*)&g_wp[0][r][k4]     = p0a;
    *(__half2*)&g_wp[0][r][k4 + 2] = p0b;
    *(__half2*)&g_wp[1][r][k4]     = p1a;
    *(__half2*)&g_wp[1][r][k4 + 2] = p1b;
}

// ---------------- main fused kernel (r7-proven structure, unchanged) ----------------
extern __shared__ char smem[];

__global__ __launch_bounds__(NTHREADS, 2)
void router_hmma_kernel(const float* __restrict__ x,
                        const float* __restrict__ rb,
                        const float* __restrict__ nb,
                        const float* __restrict__ u,
                        float* __restrict__ out,
                        int M)
{
    const int tid  = threadIdx.x;
    const int wid  = tid >> 5;
    const int lane = tid & 31;
    const int m0   = blockIdx.x * TM;
    const uint32_t sb = smem_u32(smem);

    if (tid == 0) {
#pragma unroll
        for (int s = 0; s < STAGES; s++) {
            mbar_init(sb + s * 16, NPROD);             // full: 64 producer arrivals
            mbar_init(sb + s * 16 + 8, NCONS_THREADS); // empty: 128 consumer arrivals
        }
    }
    __syncthreads();

    if (wid >= 4) {
        // ================= PRODUCER (warps 4-5, 64 threads) =================
        const int ptid = tid - NCONS_THREADS;
        float4 av[16];
        for (int c = 0; c < NC; c++) {
            const int s = c & 1;
            const uint32_t aA = sb + SM_RING + s * STAGE_BYTES;
            const uint32_t aB = aA + STAGE_A;
            mbar_wait(sb + s * 16 + 8, ((c >> 1) & 1) ^ 1);       // wait empty

            // A: 64 rows x 16 float4, all LDGs issued upfront
#pragma unroll
            for (int i = 0; i < 16; i++) {
                int q = ptid + i * NPROD;
                int row = q >> 4, kq = q & 15;
                av[i] = *(const float4*)(x + (size_t)(m0 + row) * DDIM + c * KC + kq * 4);
            }
            // B: 2 planes x 128 rows x 8 16B-cells = 2048 cells, 32/thread (async)
#pragma unroll
            for (int i = 0; i < 32; i++) {
                int q = ptid + i * NPROD;
                int pl = q >> 10, rem = q & 1023, row = rem >> 3, cg = rem & 7;
                uint32_t dst = aB + pl * B_PL + row * RSTRIDE + cg * 16;
                CPASYNC16(dst, &g_wp[pl][row][c * KC + cg * 8]);
            }
            asm volatile("cp.async.commit_group;" ::: "memory");

#pragma unroll
            for (int i = 0; i < 16; i++) {
                int q = ptid + i * NPROD;
                int row = q >> 4, kq = q & 15;
                uint32_t p0a, p1a, p0b, p1b;
                split2(av[i].x, av[i].y, p0a, p1a);
                split2(av[i].z, av[i].w, p0b, p1b);
                uint32_t base = (aA - sb) + row * RSTRIDE + kq * 8;
                *(uint2*)(smem + base + 0 * A_PL) = make_uint2(p0a, p0b);
                *(uint2*)(smem + base + 1 * A_PL) = make_uint2(p1a, p1b);
            }
            asm volatile("cp.async.wait_group 0;" ::: "memory");
            mbar_arrive(sb + s * 16);                              // full
        }
    } else {
        // ================= CONSUMER (warps 0-3, 128 threads) =================
        const int wm = wid >> 1;   // 0..1 -> 32-row slab
        const int wn = wid & 1;    // 0..1 -> 64-col slab

        uint32_t aoff[2], boff[4];
#pragma unroll
        for (int mt = 0; mt < 2; mt++) {
            int row = wm * 32 + mt * 16 + (lane & 7) + 8 * ((lane >> 3) & 1);
            aoff[mt] = (uint32_t)(row * RSTRIDE + 16 * ((lane >> 4) & 1));
        }
#pragma unroll
        for (int ntp = 0; ntp < 4; ntp++) {
            int row = wn * 64 + ntp * 16 + ((lane >> 4) & 1) * 8 + (lane & 7);
            boff[ntp] = (uint32_t)(row * RSTRIDE + 16 * ((lane >> 3) & 1));
        }

        float acc[2][8][4];
#pragma unroll
        for (int mt = 0; mt < 2; mt++)
#pragma unroll
            for (int nt = 0; nt < 8; nt++)
#pragma unroll
                for (int e = 0; e < 4; e++) acc[mt][nt][e] = 0.f;

        for (int c = 0; c < NC; c++) {
            const int s = c & 1;
            const uint32_t aA = sb + SM_RING + s * STAGE_BYTES;
            const uint32_t aB = aA + STAGE_A;
            mbar_wait(sb + s * 16, (c >> 1) & 1);                  // wait full

#pragma unroll
            for (int ks = 0; ks < 4; ks++) {
                uint32_t a0[2][4], a1[2][4], b0[8][2], b1[8][2];
#pragma unroll
                for (int mt = 0; mt < 2; mt++) {
                    LDSM4(a0[mt], aA + 0 * A_PL + ks * 32 + aoff[mt]);
                    LDSM4(a1[mt], aA + 1 * A_PL + ks * 32 + aoff[mt]);
                }
#pragma unroll
                for (int ntp = 0; ntp < 4; ntp++) {
                    uint32_t t4[4];
                    LDSM4(t4, aB + 0 * B_PL + ks * 32 + boff[ntp]);
                    b0[2 * ntp][0] = t4[0]; b0[2 * ntp][1] = t4[1];
                    b0[2 * ntp + 1][0] = t4[2]; b0[2 * ntp + 1][1] = t4[3];
                }
                // q00: x0*w0 (b1 LDSM latency hides under these)
#pragma unroll
                for (int mt = 0; mt < 2; mt++)
#pragma unroll
                    for (int nt = 0; nt < 8; nt++)
                        MMA16816(acc[mt][nt], a0[mt], b0[nt]);
#pragma unroll
                for (int ntp = 0; ntp < 4; ntp++) {
                    uint32_t t4[4];
                    LDSM4(t4, aB + 1 * B_PL + ks * 32 + boff[ntp]);
                    b1[2 * ntp][0] = t4[0]; b1[2 * ntp][1] = t4[1];
                    b1[2 * ntp + 1][0] = t4[2]; b1[2 * ntp + 1][1] = t4[3];
                }
                // q10: x1*w0
#pragma unroll
                for (int mt = 0; mt < 2; mt++)
#pragma unroll
                    for (int nt = 0; nt < 8; nt++)
                        MMA16816(acc[mt][nt], a1[mt], b0[nt]);
                // q01: x0*w1
#pragma unroll
                for (int mt = 0; mt < 2; mt++)
#pragma unroll
                    for (int nt = 0; nt < 8; nt++)
                        MMA16816(acc[mt][nt], a0[mt], b1[nt]);
            }
            mbar_arrive(sb + s * 16 + 8);                          // arrive empty
        }

        __syncthreads();   // ring dead, safe to reuse
        float* acc_s = (float*)(smem + SM_RING);
#pragma unroll
        for (int mt = 0; mt < 2; mt++)
#pragma unroll
            for (int nt = 0; nt < 8; nt++) {
                int r   = wm * 32 + mt * 16 + (lane >> 2);
                int col = wn * 64 + nt * 8 + (lane & 3) * 2;
                acc_s[r * AS + col]           = acc[mt][nt][0];
                acc_s[r * AS + col + 1]       = acc[mt][nt][1];
                acc_s[(r + 8) * AS + col]     = acc[mt][nt][2];
                acc_s[(r + 8) * AS + col + 1] = acc[mt][nt][3];
            }
    }
    if (wid >= 4) __syncthreads();   // producers join the same barrier

    // ---- noise_u tile (all threads) ----
    float* acc_s = (float*)(smem + SM_RING);
    float* su    = acc_s + TM * AS;
    {
        const float* ug = u + (size_t)m0 * NEXP;
        for (int q = tid; q < TM * NEXP; q += NTHREADS) {
            int r = q >> 6, cn = q & 63;
            su[r * US + cn] = ug[(size_t)r * NEXP + cn];
        }
    }
    __syncthreads();

    // ---- per-token epilogue ----
    if (tid < TM) {
        const int m = m0 + tid;
        float* row = acc_s + tid * AS;
        const float* urow = su + tid * US;

        float v1 = -INFINITY, v2 = -INFINITY;
        int i1 = 0, i2 = 0;
        for (int e = 0; e < NEXP; e++) {
            float lg = row[e] * INVSCALE + rb[e];
            float nz = row[NEXP + e] * INVSCALE + nb[e];
            float sp = fmaxf(nz, 0.f) + log1pf(expf(-fabsf(nz)));
            float nv = lg + sp * urow[e];
            if (nv > v1) { v2 = v1; i2 = i1; v1 = nv; i1 = e; }
            else if (nv > v2) { v2 = nv; i2 = e; }
        }
        float e2 = expf(v2 - v1);
        float den = 1.f + e2;
        float p1 = 1.f / den;
        float p2 = e2 / den;

        for (int e = 0; e < NEXP; e++) row[e] = 0.f;
        row[i1] = p1;
        row[i2] = p2;

        float* oid = out + (size_t)M * NEXP;
        oid[(size_t)m * 2 + 0] = (float)i1;
        oid[(size_t)m * 2 + 1] = (float)i2;
    }
    __syncthreads();

    // coalesced probability writeback
    for (int t = tid; t < TM * (NEXP / 4); t += NTHREADS) {
        int r = t >> 4;
        int c4 = (t & 15) * 4;
        float4 v = make_float4(acc_s[r * AS + c4 + 0],
                               acc_s[r * AS + c4 + 1],
                               acc_s[r * AS + c4 + 2],
                               acc_s[r * AS + c4 + 3]);
        *(float4*)(out + (size_t)(m0 + r) * NEXP + c4) = v;
    }
}

extern "C" void kernel_launch(void* const* d_in, const int* in_sizes, int n_in,
                              void* d_out, int out_size)
{
    const float* x  = (const float*)d_in[0];
    const float* rw = (const float*)d_in[1];
    const float* rb = (const float*)d_in[2];
    const float* nw = (const float*)d_in[3];
    const float* nb = (const float*)d_in[4];
    const float* u  = (const float*)d_in[5];

    const int M = in_sizes[0] / DDIM;  // 16384

    static bool attr_set = false;
    if (!attr_set) {
        cudaFuncSetAttribute(router_hmma_kernel,
                             cudaFuncAttributeMaxDynamicSharedMemorySize,
                             SMEM_BYTES);
        attr_set = true;
    }

    prep_w_kernel<<<(NCOL * DDIM / 4) / 256, 256>>>(rw, nw);
    router_hmma_kernel<<<M / TM, NTHREADS, SMEM_BYTES>>>(x, rb, nb, u, (float*)d_out, M);
}

// round 14
// speedup vs baseline: 2.7402x; 1.0227x over previous
#include <cuda_runtime.h>
#include <cuda_fp16.h>
#include <math.h>
#include <stdint.h>

#define DDIM   2048
#define NEXP   64
#define NCOL   128            // router(64) | noise(64) output columns
#define TM     64             // tokens per CTA
#define KC     64             // K elems per chunk
#define NC     (DDIM / KC)    // 32 chunks
#define NTHREADS 192          // 4 consumer warps + 2 producer warps
#define NPROD  64
#define NCONS_THREADS 128
#define AS     133
#define US     65
#define WSCALE 2048.0f
#define INVSCALE (1.0f / 2048.0f)

#define RSTRIDE 144                    // smem row stride bytes (128B data + 16B pad)
#define A_PL    (TM  * RSTRIDE)        // 9216  B per A plane (64 rows)
#define B_PL    (NCOL * RSTRIDE)       // 18432 B per B plane (128 rows)
#define STAGE_A (2 * A_PL)             // 18432
#define STAGE_BYTES (STAGE_A + 2 * B_PL)   // 55296
#define STAGES  2
#define SM_RING 1024
#define SMEM_BYTES (SM_RING + STAGES * STAGE_BYTES)   // 111616 (x2 CTAs/SM)

// pre-split W planes, scaled by 2048 (router rows 0..63, noise rows 64..127)
__device__ __half g_wp[2][NCOL][DDIM];

// ---------------- helpers ----------------
__device__ __forceinline__ uint32_t smem_u32(const void* p) {
    uint32_t a;
    asm("{ .reg .u64 t; cvta.to.shared.u64 t, %1; cvt.u32.u64 %0, t; }" : "=r"(a) : "l"(p));
    return a;
}
__device__ __forceinline__ void mbar_init(uint32_t a, uint32_t cnt) {
    asm volatile("mbarrier.init.shared.b64 [%0], %1;" :: "r"(a), "r"(cnt) : "memory");
}
__device__ __forceinline__ void mbar_arrive(uint32_t a) {
    asm volatile("mbarrier.arrive.shared.b64 _, [%0];" :: "r"(a) : "memory");
}
__device__ __forceinline__ void mbar_wait(uint32_t a, uint32_t parity) {
    asm volatile(
        "{\n\t.reg .pred P1;\n\t"
        "W%=:\n\t"
        "mbarrier.try_wait.parity.acquire.cta.shared::cta.b64 P1, [%0], %1, 0x989680;\n\t"
        "@P1 bra.uni D%=;\n\t"
        "bra.uni W%=;\n\t"
        "D%=:\n\t}"
        :: "r"(a), "r"(parity) : "memory");
}
// 2-way fp16 split of a float pair (lo,hi) -> 2 f16x2 regs
__device__ __forceinline__ void split2(float lo, float hi, uint32_t& u0, uint32_t& u1) {
    __half2 h0 = __floats2half2_rn(lo, hi);
    float l0 = __half2float(__low2half(h0));
    float hh = __half2float(__high2half(h0));
    __half2 h1 = __floats2half2_rn(lo - l0, hi - hh);
    u0 = *reinterpret_cast<uint32_t*>(&h0);
    u1 = *reinterpret_cast<uint32_t*>(&h1);
}
#define LDSM4(r, a) \
    asm volatile("ldmatrix.sync.aligned.m8n8.x4.shared.b16 {%0,%1,%2,%3}, [%4];" \
        : "=r"((r)[0]), "=r"((r)[1]), "=r"((r)[2]), "=r"((r)[3]) : "r"(a))
#define MMA16816(d, a, b) \
    asm volatile("mma.sync.aligned.m16n8k16.row.col.f32.f16.f16.f32 " \
        "{%0,%1,%2,%3}, {%4,%5,%6,%7}, {%8,%9}, {%0,%1,%2,%3};" \
        : "+f"((d)[0]), "+f"((d)[1]), "+f"((d)[2]), "+f"((d)[3]) \
        : "r"((a)[0]), "r"((a)[1]), "r"((a)[2]), "r"((a)[3]), "r"((b)[0]), "r"((b)[1]))
#define CPASYNC16(dst, src) \
    asm volatile("cp.async.cg.shared.global [%0], [%1], 16;" :: "r"(dst), "l"(src) : "memory")

// ---------------- prep: split W into 2 scaled fp16 planes (vectorized) ----------------
__global__ void prep_w_kernel(const float* __restrict__ rw, const float* __restrict__ nw) {
    int idx = blockIdx.x * blockDim.x + threadIdx.x;      // 0 .. 65535
    int r  = idx >> 9;                                    // row 0..127
    int k4 = (idx & 511) * 4;                             // k offset, /4 aligned
    const float* src = (r < NEXP) ? (rw + (size_t)r * DDIM)
                                  : (nw + (size_t)(r - NEXP) * DDIM);
    float4 v = *(const float4*)(src + k4);
    v.x *= WSCALE; v.y *= WSCALE; v.z *= WSCALE; v.w *= WSCALE;

    __half2 p0a = __floats2half2_rn(v.x, v.y);
    __half2 p0b = __floats2half2_rn(v.z, v.w);
    float r0 = v.x - __half2float(__low2half(p0a));
    float r1 = v.y - __half2float(__high2half(p0a));
    float r2 = v.z - __half2float(__low2half(p0b));
    float r3 = v.w - __half2float(__high2half(p0b));
    __half2 p1a = __floats2half2_rn(r0, r1);
    __half2 p1b = __floats2half2_rn(r2, r3);

    *(__half2*)&g_wp[0][r][k4]     = p0a;
    *(__half2*)&g_wp[0][r][k4 + 2] = p0b;
    *(__half2*)&g_wp[1][r][k4]     = p1a;
    *(__half2*)&g_wp[1][r][k4 + 2] = p1b;
}

// ---------------- main fused kernel ----------------
extern __shared__ char smem[];

__global__ __launch_bounds__(NTHREADS, 2)
void router_hmma_kernel(const float* __restrict__ x,
                        const float* __restrict__ rb,
                        const float* __restrict__ nb,
                        const float* __restrict__ u,
                        float* __restrict__ out,
                        int M)
{
    const int tid  = threadIdx.x;
    const int wid  = tid >> 5;
    const int lane = tid & 31;
    const int m0   = blockIdx.x * TM;
    const uint32_t sb = smem_u32(smem);

    if (tid == 0) {
#pragma unroll
        for (int s = 0; s < STAGES; s++) {
            mbar_init(sb + s * 16, NPROD);             // full: 64 producer arrivals
            mbar_init(sb + s * 16 + 8, NCONS_THREADS); // empty: 128 consumer arrivals
        }
    }
    __syncthreads();

    float* acc_s = (float*)(smem + SM_RING);   // [TM][AS] (reuses dead ring later)
    float* su    = acc_s + TM * AS;            // [TM][US]
    float ureg[64];                            // producer-only u stash

    if (wid >= 4) {
        // ================= PRODUCER (warps 4-5, 64 threads) =================
        const int ptid = tid - NCONS_THREADS;
        float4 av[16];
        for (int c = 0; c < NC; c++) {
            const int s = c & 1;
            const uint32_t aA = sb + SM_RING + s * STAGE_BYTES;
            const uint32_t aB = aA + STAGE_A;
            mbar_wait(sb + s * 16 + 8, ((c >> 1) & 1) ^ 1);       // wait empty

            // A: 64 rows x 16 float4, all LDGs issued upfront
#pragma unroll
            for (int i = 0; i < 16; i++) {
                int q = ptid + i * NPROD;
                int row = q >> 4, kq = q & 15;
                av[i] = *(const float4*)(x + (size_t)(m0 + row) * DDIM + c * KC + kq * 4);
            }
            // B: 2 planes x 128 rows x 8 16B-cells = 2048 cells, 32/thread (async)
#pragma unroll
            for (int i = 0; i < 32; i++) {
                int q = ptid + i * NPROD;
                int pl = q >> 10, rem = q & 1023, row = rem >> 3, cg = rem & 7;
                uint32_t dst = aB + pl * B_PL + row * RSTRIDE + cg * 16;
                CPASYNC16(dst, &g_wp[pl][row][c * KC + cg * 8]);
            }
            asm volatile("cp.async.commit_group;" ::: "memory");

#pragma unroll
            for (int i = 0; i < 16; i++) {
                int q = ptid + i * NPROD;
                int row = q >> 4, kq = q & 15;
                uint32_t p0a, p1a, p0b, p1b;
                split2(av[i].x, av[i].y, p0a, p1a);
                split2(av[i].z, av[i].w, p0b, p1b);
                uint32_t base = (aA - sb) + row * RSTRIDE + kq * 8;
                *(uint2*)(smem + base + 0 * A_PL) = make_uint2(p0a, p0b);
                *(uint2*)(smem + base + 1 * A_PL) = make_uint2(p1a, p1b);
            }
            asm volatile("cp.async.wait_group 0;" ::: "memory");
            mbar_arrive(sb + s * 16);                              // full
        }
        // ring done for producers: prefetch this CTA's u tile into registers
        // (hidden under consumers' final MMA chunks). One token per thread.
        {
            const float* ur = u + (size_t)(m0 + ptid) * NEXP;
#pragma unroll
            for (int e = 0; e < 16; e++)
                *(float4*)&ureg[e * 4] = *(const float4*)(ur + e * 4);
        }
        __syncthreads();   // join: consumers finished, ring dead
        // store u stash to smem while consumers stage acc_s
        {
            float* srow = su + ptid * US;
#pragma unroll
            for (int e = 0; e < 64; e++) srow[e] = ureg[e];
        }
    } else {
        // ================= CONSUMER (warps 0-3, 128 threads) =================
        const int wm = wid >> 1;   // 0..1 -> 32-row slab
        const int wn = wid & 1;    // 0..1 -> 64-col slab

        uint32_t aoff[2], boff[4];
#pragma unroll
        for (int mt = 0; mt < 2; mt++) {
            int row = wm * 32 + mt * 16 + (lane & 7) + 8 * ((lane >> 3) & 1);
            aoff[mt] = (uint32_t)(row * RSTRIDE + 16 * ((lane >> 4) & 1));
        }
#pragma unroll
        for (int ntp = 0; ntp < 4; ntp++) {
            int row = wn * 64 + ntp * 16 + ((lane >> 4) & 1) * 8 + (lane & 7);
            boff[ntp] = (uint32_t)(row * RSTRIDE + 16 * ((lane >> 3) & 1));
        }

        float acc[2][8][4];
#pragma unroll
        for (int mt = 0; mt < 2; mt++)
#pragma unroll
            for (int nt = 0; nt < 8; nt++)
#pragma unroll
                for (int e = 0; e < 4; e++) acc[mt][nt][e] = 0.f;

        for (int c = 0; c < NC; c++) {
            const int s = c & 1;
            const uint32_t aA = sb + SM_RING + s * STAGE_BYTES;
            const uint32_t aB = aA + STAGE_A;
            mbar_wait(sb + s * 16, (c >> 1) & 1);                  // wait full

#pragma unroll
            for (int ks = 0; ks < 4; ks++) {
                uint32_t a0[2][4], a1[2][4], b0[8][2], b1[8][2];
#pragma unroll
                for (int mt = 0; mt < 2; mt++) {
                    LDSM4(a0[mt], aA + 0 * A_PL + ks * 32 + aoff[mt]);
                    LDSM4(a1[mt], aA + 1 * A_PL + ks * 32 + aoff[mt]);
                }
#pragma unroll
                for (int ntp = 0; ntp < 4; ntp++) {
                    uint32_t t4[4];
                    LDSM4(t4, aB + 0 * B_PL + ks * 32 + boff[ntp]);
                    b0[2 * ntp][0] = t4[0]; b0[2 * ntp][1] = t4[1];
                    b0[2 * ntp + 1][0] = t4[2]; b0[2 * ntp + 1][1] = t4[3];
                }
                // q00: x0*w0 (b1 LDSM latency hides under these)
#pragma unroll
                for (int mt = 0; mt < 2; mt++)
#pragma unroll
                    for (int nt = 0; nt < 8; nt++)
                        MMA16816(acc[mt][nt], a0[mt], b0[nt]);
#pragma unroll
                for (int ntp = 0; ntp < 4; ntp++) {
                    uint32_t t4[4];
                    LDSM4(t4, aB + 1 * B_PL + ks * 32 + boff[ntp]);
                    b1[2 * ntp][0] = t4[0]; b1[2 * ntp][1] = t4[1];
                    b1[2 * ntp + 1][0] = t4[2]; b1[2 * ntp + 1][1] = t4[3];
                }
                // q10: x1*w0
#pragma unroll
                for (int mt = 0; mt < 2; mt++)
#pragma unroll
                    for (int nt = 0; nt < 8; nt++)
                        MMA16816(acc[mt][nt], a1[mt], b0[nt]);
                // q01: x0*w1
#pragma unroll
                for (int mt = 0; mt < 2; mt++)
#pragma unroll
                    for (int nt = 0; nt < 8; nt++)
                        MMA16816(acc[mt][nt], a0[mt], b1[nt]);
            }
            mbar_arrive(sb + s * 16 + 8);                          // arrive empty
        }

        __syncthreads();   // join: ring dead, safe to reuse
#pragma unroll
        for (int mt = 0; mt < 2; mt++)
#pragma unroll
            for (int nt = 0; nt < 8; nt++) {
                int r   = wm * 32 + mt * 16 + (lane >> 2);
                int col = wn * 64 + nt * 8 + (lane & 3) * 2;
                acc_s[r * AS + col]           = acc[mt][nt][0];
                acc_s[r * AS + col + 1]       = acc[mt][nt][1];
                acc_s[(r + 8) * AS + col]     = acc[mt][nt][2];
                acc_s[(r + 8) * AS + col + 1] = acc[mt][nt][3];
            }
    }
    __syncthreads();   // acc_s + su both staged

    // ---- per-token epilogue ----
    if (tid < TM) {
        const int m = m0 + tid;
        float* row = acc_s + tid * AS;
        const float* urow = su + tid * US;

        float v1 = -INFINITY, v2 = -INFINITY;
        int i1 = 0, i2 = 0;
        for (int e = 0; e < NEXP; e++) {
            float lg = row[e] * INVSCALE + rb[e];
            float nz = row[NEXP + e] * INVSCALE + nb[e];
            float sp = fmaxf(nz, 0.f) + log1pf(expf(-fabsf(nz)));
            float nv = lg + sp * urow[e];
            if (nv > v1) { v2 = v1; i2 = i1; v1 = nv; i1 = e; }
            else if (nv > v2) { v2 = nv; i2 = e; }
        }
        float e2 = expf(v2 - v1);
        float den = 1.f + e2;
        float p1 = 1.f / den;
        float p2 = e2 / den;

        for (int e = 0; e < NEXP; e++) row[e] = 0.f;
        row[i1] = p1;
        row[i2] = p2;

        float* oid = out + (size_t)M * NEXP;
        oid[(size_t)m * 2 + 0] = (float)i1;
        oid[(size_t)m * 2 + 1] = (float)i2;
    }
    __syncthreads();

    // coalesced probability writeback
    for (int t = tid; t < TM * (NEXP / 4); t += NTHREADS) {
        int r = t >> 4;
        int c4 = (t & 15) * 4;
        float4 v = make_float4(acc_s[r * AS + c4 + 0],
                               acc_s[r * AS + c4 + 1],
                               acc_s[r * AS + c4 + 2],
                               acc_s[r * AS + c4 + 3]);
        *(float4*)(out + (size_t)(m0 + r) * NEXP + c4) = v;
    }
}

extern "C" void kernel_launch(void* const* d_in, const int* in_sizes, int n_in,
                              void* d_out, int out_size)
{
    const float* x  = (const float*)d_in[0];
    const float* rw = (const float*)d_in[1];
    const float* rb = (const float*)d_in[2];
    const float* nw = (const float*)d_in[3];
    const float* nb = (const float*)d_in[4];
    const float* u  = (const float*)d_in[5];

    const int M = in_sizes[0] / DDIM;  // 16384

    static bool attr_set = false;
    if (!attr_set) {
        cudaFuncSetAttribute(router_hmma_kernel,
                             cudaFuncAttributeMaxDynamicSharedMemorySize,
                             SMEM_BYTES);
        attr_set = true;
    }

    prep_w_kernel<<<(NCOL * DDIM / 4) / 256, 256>>>(rw, nw);
    router_hmma_kernel<<<M / TM, NTHREADS, SMEM_BYTES>>>(x, rb, nb, u, (float*)d_out, M);
}

// round 15
// speedup vs baseline: 2.7932x; 1.0193x over previous
#include <cuda_runtime.h>
#include <cuda_fp16.h>
#include <math.h>
#include <stdint.h>

#define DDIM   2048
#define NEXP   64
#define NCOL   128            // router(64) | noise(64) output columns
#define TM     64             // tokens per CTA
#define KC     64             // K elems per chunk
#define NC     (DDIM / KC)    // 32 chunks
#define NTHREADS 192          // 4 consumer warps + 2 producer warps
#define NPROD  64
#define NCONS_THREADS 128
#define AS     133
#define US     65
#define WSCALE 2048.0f
#define INVSCALE (1.0f / 2048.0f)

#define RSTRIDE 144                    // smem row stride bytes (128B data + 16B pad)
#define A_PL    (TM  * RSTRIDE)        // 9216  B per A plane (64 rows)
#define B_PL    (NCOL * RSTRIDE)       // 18432 B per B plane (128 rows)
#define STAGE_A (2 * A_PL)             // 18432
#define STAGE_BYTES (STAGE_A + 2 * B_PL)   // 55296
#define STAGES  2
#define SM_RING 1024
#define SMEM_BYTES (SM_RING + STAGES * STAGE_BYTES)   // 111616 (x2 CTAs/SM)

// pre-split W planes, scaled by 2048 (router rows 0..63, noise rows 64..127)
__device__ __half g_wp[2][NCOL][DDIM];
__device__ unsigned int g_bar;   // monotonic epoch ticket barrier (replay-safe)

// ---------------- helpers ----------------
__device__ __forceinline__ uint32_t smem_u32(const void* p) {
    uint32_t a;
    asm("{ .reg .u64 t; cvta.to.shared.u64 t, %1; cvt.u32.u64 %0, t; }" : "=r"(a) : "l"(p));
    return a;
}
__device__ __forceinline__ void mbar_init(uint32_t a, uint32_t cnt) {
    asm volatile("mbarrier.init.shared.b64 [%0], %1;" :: "r"(a), "r"(cnt) : "memory");
}
__device__ __forceinline__ void mbar_arrive(uint32_t a) {
    asm volatile("mbarrier.arrive.shared.b64 _, [%0];" :: "r"(a) : "memory");
}
__device__ __forceinline__ void mbar_wait(uint32_t a, uint32_t parity) {
    asm volatile(
        "{\n\t.reg .pred P1;\n\t"
        "W%=:\n\t"
        "mbarrier.try_wait.parity.acquire.cta.shared::cta.b64 P1, [%0], %1, 0x989680;\n\t"
        "@P1 bra.uni D%=;\n\t"
        "bra.uni W%=;\n\t"
        "D%=:\n\t}"
        :: "r"(a), "r"(parity) : "memory");
}
// 2-way fp16 split of a float pair (lo,hi) -> 2 f16x2 regs
__device__ __forceinline__ void split2(float lo, float hi, uint32_t& u0, uint32_t& u1) {
    __half2 h0 = __floats2half2_rn(lo, hi);
    float l0 = __half2float(__low2half(h0));
    float hh = __half2float(__high2half(h0));
    __half2 h1 = __floats2half2_rn(lo - l0, hi - hh);
    u0 = *reinterpret_cast<uint32_t*>(&h0);
    u1 = *reinterpret_cast<uint32_t*>(&h1);
}
#define LDSM4(r, a) \
    asm volatile("ldmatrix.sync.aligned.m8n8.x4.shared.b16 {%0,%1,%2,%3}, [%4];" \
        : "=r"((r)[0]), "=r"((r)[1]), "=r"((r)[2]), "=r"((r)[3]) : "r"(a))
#define MMA16816(d, a, b) \
    asm volatile("mma.sync.aligned.m16n8k16.row.col.f32.f16.f16.f32 " \
        "{%0,%1,%2,%3}, {%4,%5,%6,%7}, {%8,%9}, {%0,%1,%2,%3};" \
        : "+f"((d)[0]), "+f"((d)[1]), "+f"((d)[2]), "+f"((d)[3]) \
        : "r"((a)[0]), "r"((a)[1]), "r"((a)[2]), "r"((a)[3]), "r"((b)[0]), "r"((b)[1]))
#define CPASYNC16(dst, src) \
    asm volatile("cp.async.cg.shared.global [%0], [%1], 16;" :: "r"(dst), "l"(src) : "memory")

// ---------------- main fused kernel (single launch) ----------------
extern __shared__ char smem[];

__global__ __launch_bounds__(NTHREADS, 2)
void router_hmma_kernel(const float* __restrict__ x,
                        const float* __restrict__ rw,
                        const float* __restrict__ rb,
                        const float* __restrict__ nw,
                        const float* __restrict__ nb,
                        const float* __restrict__ u,
                        float* __restrict__ out,
                        int M)
{
    const int tid  = threadIdx.x;
    const int wid  = tid >> 5;
    const int lane = tid & 31;
    const int m0   = blockIdx.x * TM;
    const uint32_t sb = smem_u32(smem);

    // ======== inline W prep: this CTA splits its 1/gridDim slice ========
    // total 65536 float4 work items over [2][128][2048] halves; 256 per CTA
    {
        const int base = blockIdx.x * 256;
        for (int q = tid; q < 256; q += NTHREADS) {
            int idx = base + q;              // 0 .. 65535
            int r  = idx >> 9;               // row 0..127
            int k4 = (idx & 511) * 4;        // k offset, /4 aligned
            const float* src = (r < NEXP) ? (rw + (size_t)r * DDIM)
                                          : (nw + (size_t)(r - NEXP) * DDIM);
            float4 v = *(const float4*)(src + k4);
            v.x *= WSCALE; v.y *= WSCALE; v.z *= WSCALE; v.w *= WSCALE;
            __half2 p0a = __floats2half2_rn(v.x, v.y);
            __half2 p0b = __floats2half2_rn(v.z, v.w);
            float r0 = v.x - __half2float(__low2half(p0a));
            float r1 = v.y - __half2float(__high2half(p0a));
            float r2 = v.z - __half2float(__low2half(p0b));
            float r3 = v.w - __half2float(__high2half(p0b));
            __half2 p1a = __floats2half2_rn(r0, r1);
            __half2 p1b = __floats2half2_rn(r2, r3);
            *(__half2*)&g_wp[0][r][k4]     = p0a;
            *(__half2*)&g_wp[0][r][k4 + 2] = p0b;
            *(__half2*)&g_wp[1][r][k4]     = p1a;
            *(__half2*)&g_wp[1][r][k4 + 2] = p1b;
        }
    }
    // grid-wide ticket barrier (all 256 CTAs co-resident: 2/SM x 148 = 296 slots)
    __syncthreads();
    if (tid == 0) {
        __threadfence();   // make g_wp slice visible GPU-wide (L2)
        unsigned int ticket = atomicAdd(&g_bar, 1u);
        unsigned int target = (ticket / gridDim.x + 1u) * gridDim.x;
        unsigned int v;
        do {
            asm volatile("ld.global.cg.u32 %0, [%1];" : "=r"(v) : "l"(&g_bar));
            if (v < target) __nanosleep(128);
        } while (v < target);
        __threadfence();   // acquire

        // mbarrier init (moved here: one thread, post-barrier)
#pragma unroll
        for (int s = 0; s < STAGES; s++) {
            mbar_init(sb + s * 16, NPROD);             // full: 64 producer arrivals
            mbar_init(sb + s * 16 + 8, NCONS_THREADS); // empty: 128 consumer arrivals
        }
    }
    __syncthreads();

    float* acc_s = (float*)(smem + SM_RING);   // [TM][AS] (reuses dead ring later)
    float* su    = acc_s + TM * AS;            // [TM][US]
    float ureg[64];                            // producer-only u stash

    if (wid >= 4) {
        // ================= PRODUCER (warps 4-5, 64 threads) =================
        const int ptid = tid - NCONS_THREADS;
        float4 av[16];
        for (int c = 0; c < NC; c++) {
            const int s = c & 1;
            const uint32_t aA = sb + SM_RING + s * STAGE_BYTES;
            const uint32_t aB = aA + STAGE_A;
            mbar_wait(sb + s * 16 + 8, ((c >> 1) & 1) ^ 1);       // wait empty

            // A: 64 rows x 16 float4, all LDGs issued upfront
#pragma unroll
            for (int i = 0; i < 16; i++) {
                int q = ptid + i * NPROD;
                int row = q >> 4, kq = q & 15;
                av[i] = *(const float4*)(x + (size_t)(m0 + row) * DDIM + c * KC + kq * 4);
            }
            // B: 2 planes x 128 rows x 8 16B-cells = 2048 cells, 32/thread (async)
#pragma unroll
            for (int i = 0; i < 32; i++) {
                int q = ptid + i * NPROD;
                int pl = q >> 10, rem = q & 1023, row = rem >> 3, cg = rem & 7;
                uint32_t dst = aB + pl * B_PL + row * RSTRIDE + cg * 16;
                CPASYNC16(dst, &g_wp[pl][row][c * KC + cg * 8]);
            }
            asm volatile("cp.async.commit_group;" ::: "memory");

#pragma unroll
            for (int i = 0; i < 16; i++) {
                int q = ptid + i * NPROD;
                int row = q >> 4, kq = q & 15;
                uint32_t p0a, p1a, p0b, p1b;
                split2(av[i].x, av[i].y, p0a, p1a);
                split2(av[i].z, av[i].w, p0b, p1b);
                uint32_t base = (aA - sb) + row * RSTRIDE + kq * 8;
                *(uint2*)(smem + base + 0 * A_PL) = make_uint2(p0a, p0b);
                *(uint2*)(smem + base + 1 * A_PL) = make_uint2(p1a, p1b);
            }
            asm volatile("cp.async.wait_group 0;" ::: "memory");
            mbar_arrive(sb + s * 16);                              // full
        }
        // ring done: prefetch this CTA's u tile into registers (hidden under
        // consumers' final MMA chunks). One token per thread.
        {
            const float* ur = u + (size_t)(m0 + ptid) * NEXP;
#pragma unroll
            for (int e = 0; e < 16; e++)
                *(float4*)&ureg[e * 4] = *(const float4*)(ur + e * 4);
        }
        __syncthreads();   // join: consumers finished, ring dead
        {
            float* srow = su + ptid * US;
#pragma unroll
            for (int e = 0; e < 64; e++) srow[e] = ureg[e];
        }
    } else {
        // ================= CONSUMER (warps 0-3, 128 threads) =================
        const int wm = wid >> 1;   // 0..1 -> 32-row slab
        const int wn = wid & 1;    // 0..1 -> 64-col slab

        uint32_t aoff[2], boff[4];
#pragma unroll
        for (int mt = 0; mt < 2; mt++) {
            int row = wm * 32 + mt * 16 + (lane & 7) + 8 * ((lane >> 3) & 1);
            aoff[mt] = (uint32_t)(row * RSTRIDE + 16 * ((lane >> 4) & 1));
        }
#pragma unroll
        for (int ntp = 0; ntp < 4; ntp++) {
            int row = wn * 64 + ntp * 16 + ((lane >> 4) & 1) * 8 + (lane & 7);
            boff[ntp] = (uint32_t)(row * RSTRIDE + 16 * ((lane >> 3) & 1));
        }

        float acc[2][8][4];
#pragma unroll
        for (int mt = 0; mt < 2; mt++)
#pragma unroll
            for (int nt = 0; nt < 8; nt++)
#pragma unroll
                for (int e = 0; e < 4; e++) acc[mt][nt][e] = 0.f;

        for (int c = 0; c < NC; c++) {
            const int s = c & 1;
            const uint32_t aA = sb + SM_RING + s * STAGE_BYTES;
            const uint32_t aB = aA + STAGE_A;
            mbar_wait(sb + s * 16, (c >> 1) & 1);                  // wait full

#pragma unroll
            for (int ks = 0; ks < 4; ks++) {
                uint32_t a0[2][4], a1[2][4], b0[8][2], b1[8][2];
#pragma unroll
                for (int mt = 0; mt < 2; mt++) {
                    LDSM4(a0[mt], aA + 0 * A_PL + ks * 32 + aoff[mt]);
                    LDSM4(a1[mt], aA + 1 * A_PL + ks * 32 + aoff[mt]);
                }
#pragma unroll
                for (int ntp = 0; ntp < 4; ntp++) {
                    uint32_t t4[4];
                    LDSM4(t4, aB + 0 * B_PL + ks * 32 + boff[ntp]);
                    b0[2 * ntp][0] = t4[0]; b0[2 * ntp][1] = t4[1];
                    b0[2 * ntp + 1][0] = t4[2]; b0[2 * ntp + 1][1] = t4[3];
                }
                // q00: x0*w0 (b1 LDSM latency hides under these)
#pragma unroll
                for (int mt = 0; mt < 2; mt++)
#pragma unroll
                    for (int nt = 0; nt < 8; nt++)
                        MMA16816(acc[mt][nt], a0[mt], b0[nt]);
#pragma unroll
                for (int ntp = 0; ntp < 4; ntp++) {
                    uint32_t t4[4];
                    LDSM4(t4, aB + 1 * B_PL + ks * 32 + boff[ntp]);
                    b1[2 * ntp][0] = t4[0]; b1[2 * ntp][1] = t4[1];
                    b1[2 * ntp + 1][0] = t4[2]; b1[2 * ntp + 1][1] = t4[3];
                }
                // q10: x1*w0
#pragma unroll
                for (int mt = 0; mt < 2; mt++)
#pragma unroll
                    for (int nt = 0; nt < 8; nt++)
                        MMA16816(acc[mt][nt], a1[mt], b0[nt]);
                // q01: x0*w1
#pragma unroll
                for (int mt = 0; mt < 2; mt++)
#pragma unroll
                    for (int nt = 0; nt < 8; nt++)
                        MMA16816(acc[mt][nt], a0[mt], b1[nt]);
            }
            mbar_arrive(sb + s * 16 + 8);                          // arrive empty
        }

        __syncthreads();   // join: ring dead, safe to reuse
#pragma unroll
        for (int mt = 0; mt < 2; mt++)
#pragma unroll
            for (int nt = 0; nt < 8; nt++) {
                int r   = wm * 32 + mt * 16 + (lane >> 2);
                int col = wn * 64 + nt * 8 + (lane & 3) * 2;
                acc_s[r * AS + col]           = acc[mt][nt][0];
                acc_s[r * AS + col + 1]       = acc[mt][nt][1];
                acc_s[(r + 8) * AS + col]     = acc[mt][nt][2];
                acc_s[(r + 8) * AS + col + 1] = acc[mt][nt][3];
            }
    }
    __syncthreads();   // acc_s + su both staged

    // ---- per-token epilogue ----
    if (tid < TM) {
        const int m = m0 + tid;
        float* row = acc_s + tid * AS;
        const float* urow = su + tid * US;

        float v1 = -INFINITY, v2 = -INFINITY;
        int i1 = 0, i2 = 0;
        for (int e = 0; e < NEXP; e++) {
            float lg = row[e] * INVSCALE + rb[e];
            float nz = row[NEXP + e] * INVSCALE + nb[e];
            float sp = fmaxf(nz, 0.f) + log1pf(expf(-fabsf(nz)));
            float nv = lg + sp * urow[e];
            if (nv > v1) { v2 = v1; i2 = i1; v1 = nv; i1 = e; }
            else if (nv > v2) { v2 = nv; i2 = e; }
        }
        float e2 = expf(v2 - v1);
        float den = 1.f + e2;
        float p1 = 1.f / den;
        float p2 = e2 / den;

        for (int e = 0; e < NEXP; e++) row[e] = 0.f;
        row[i1] = p1;
        row[i2] = p2;

        float* oid = out + (size_t)M * NEXP;
        oid[(size_t)m * 2 + 0] = (float)i1;
        oid[(size_t)m * 2 + 1] = (float)i2;
    }
    __syncthreads();

    // coalesced probability writeback
    for (int t = tid; t < TM * (NEXP / 4); t += NTHREADS) {
        int r = t >> 4;
        int c4 = (t & 15) * 4;
        float4 v = make_float4(acc_s[r * AS + c4 + 0],
                               acc_s[r * AS + c4 + 1],
                               acc_s[r * AS + c4 + 2],
                               acc_s[r * AS + c4 + 3]);
        *(float4*)(out + (size_t)(m0 + r) * NEXP + c4) = v;
    }
}

extern "C" void kernel_launch(void* const* d_in, const int* in_sizes, int n_in,
                              void* d_out, int out_size)
{
    const float* x  = (const float*)d_in[0];
    const float* rw = (const float*)d_in[1];
    const float* rb = (const float*)d_in[2];
    const float* nw = (const float*)d_in[3];
    const float* nb = (const float*)d_in[4];
    const float* u  = (const float*)d_in[5];

    const int M = in_sizes[0] / DDIM;  // 16384

    static bool attr_set = false;
    if (!attr_set) {
        cudaFuncSetAttribute(router_hmma_kernel,
                             cudaFuncAttributeMaxDynamicSharedMemorySize,
                             SMEM_BYTES);
        attr_set = true;
    }

    router_hmma_kernel<<<M / TM, NTHREADS, SMEM_BYTES>>>(x, rw, rb, nw, nb, u,
                                                         (float*)d_out, M);
}

// round 16
// speedup vs baseline: 3.0828x; 1.1037x over previous
#include <cuda_runtime.h>
#include <cuda_fp16.h>
#include <math.h>
#include <stdint.h>

#define DDIM   2048
#define NEXP   64
#define NCOL   128            // router(64) | noise(64) output columns
#define TM     64             // tokens per CTA
#define KC     64             // K elems per chunk
#define NC     (DDIM / KC)    // 32 chunks
#define NTHREADS 192          // 4 consumer warps + 2 producer warps
#define NPROD  64
#define NCONS_THREADS 128
#define AS     133
#define US     65
#define WSCALE 2048.0f
#define INVSCALE (1.0f / 2048.0f)
#define TAU    3e-3f          // flag margin (>= 2 * 7.5sigma of noise-path error)

#define RSTRIDE 144                    // smem row stride bytes (128B data + 16B pad)
#define A_PL    (TM  * RSTRIDE)        // 9216
#define B_PL    (NCOL * RSTRIDE)       // 18432
#define STAGE_A (2 * A_PL)             // 18432
#define STAGE_BYTES (STAGE_A + 2 * B_PL)   // 55296
#define STAGES  2
#define SM_RING 1024
#define SMEM_BYTES (SM_RING + STAGES * STAGE_BYTES)   // 111616 (x2 CTAs/SM)

// epilogue smem layout (overlaps dead ring)
#define OFF_ACC   SM_RING                       // [64][133] f32 -> 34048 B
#define OFF_SU    (OFF_ACC + TM * AS * 4)       // [64][65]  f32 -> 16640 B
#define OFF_I1    (OFF_SU + TM * US * 4)        // int[64]
#define OFF_I2    (OFF_I1 + 256)
#define OFF_P1    (OFF_I2 + 256)
#define OFF_P2    (OFF_P1 + 256)
#define OFF_V2A   (OFF_P2 + 256)
#define OFF_LIST  (OFF_V2A + 256)
#define OFF_NF    (OFF_LIST + 256)
#define OFF_SX    (OFF_NF + 16)                 // 6 warps x 2048 f32 = 49152 B
// OFF_SX + 49152 = ~102.6KB <= 111616  OK

// pre-split W planes, scaled by 2048 (router rows 0..63, noise rows 64..127)
__device__ __half g_wp[2][NCOL][DDIM];
__device__ unsigned int g_bar;   // monotonic epoch ticket barrier (replay-safe)

// ---------------- helpers ----------------
__device__ __forceinline__ uint32_t smem_u32(const void* p) {
    uint32_t a;
    asm("{ .reg .u64 t; cvta.to.shared.u64 t, %1; cvt.u32.u64 %0, t; }" : "=r"(a) : "l"(p));
    return a;
}
__device__ __forceinline__ void mbar_init(uint32_t a, uint32_t cnt) {
    asm volatile("mbarrier.init.shared.b64 [%0], %1;" :: "r"(a), "r"(cnt) : "memory");
}
__device__ __forceinline__ void mbar_arrive(uint32_t a) {
    asm volatile("mbarrier.arrive.shared.b64 _, [%0];" :: "r"(a) : "memory");
}
__device__ __forceinline__ void mbar_wait(uint32_t a, uint32_t parity) {
    asm volatile(
        "{\n\t.reg .pred P1;\n\t"
        "W%=:\n\t"
        "mbarrier.try_wait.parity.acquire.cta.shared::cta.b64 P1, [%0], %1, 0x989680;\n\t"
        "@P1 bra.uni D%=;\n\t"
        "bra.uni W%=;\n\t"
        "D%=:\n\t}"
        :: "r"(a), "r"(parity) : "memory");
}
__device__ __forceinline__ void split2(float lo, float hi, uint32_t& u0, uint32_t& u1) {
    __half2 h0 = __floats2half2_rn(lo, hi);
    float l0 = __half2float(__low2half(h0));
    float hh = __half2float(__high2half(h0));
    __half2 h1 = __floats2half2_rn(lo - l0, hi - hh);
    u0 = *reinterpret_cast<uint32_t*>(&h0);
    u1 = *reinterpret_cast<uint32_t*>(&h1);
}
#define LDSM4(r, a) \
    asm volatile("ldmatrix.sync.aligned.m8n8.x4.shared.b16 {%0,%1,%2,%3}, [%4];" \
        : "=r"((r)[0]), "=r"((r)[1]), "=r"((r)[2]), "=r"((r)[3]) : "r"(a))
#define MMA16816(d, a, b) \
    asm volatile("mma.sync.aligned.m16n8k16.row.col.f32.f16.f16.f32 " \
        "{%0,%1,%2,%3}, {%4,%5,%6,%7}, {%8,%9}, {%0,%1,%2,%3};" \
        : "+f"((d)[0]), "+f"((d)[1]), "+f"((d)[2]), "+f"((d)[3]) \
        : "r"((a)[0]), "r"((a)[1]), "r"((a)[2]), "r"((a)[3]), "r"((b)[0]), "r"((b)[1]))
#define CPASYNC16(dst, src) \
    asm volatile("cp.async.cg.shared.global [%0], [%1], 16;" :: "r"(dst), "l"(src) : "memory")

// ---------------- main fused kernel (single launch) ----------------
extern __shared__ char smem[];

__global__ __launch_bounds__(NTHREADS, 2)
void router_hmma_kernel(const float* __restrict__ x,
                        const float* __restrict__ rw,
                        const float* __restrict__ rb,
                        const float* __restrict__ nw,
                        const float* __restrict__ nb,
                        const float* __restrict__ u,
                        float* __restrict__ out,
                        int M)
{
    const int tid  = threadIdx.x;
    const int wid  = tid >> 5;
    const int lane = tid & 31;
    const int m0   = blockIdx.x * TM;
    const uint32_t sb = smem_u32(smem);

    // ======== inline W prep: this CTA splits its 1/gridDim slice ========
    {
        const int base = blockIdx.x * 256;
        for (int q = tid; q < 256; q += NTHREADS) {
            int idx = base + q;
            int r  = idx >> 9;
            int k4 = (idx & 511) * 4;
            const float* src = (r < NEXP) ? (rw + (size_t)r * DDIM)
                                          : (nw + (size_t)(r - NEXP) * DDIM);
            float4 v = *(const float4*)(src + k4);
            v.x *= WSCALE; v.y *= WSCALE; v.z *= WSCALE; v.w *= WSCALE;
            __half2 p0a = __floats2half2_rn(v.x, v.y);
            __half2 p0b = __floats2half2_rn(v.z, v.w);
            float r0 = v.x - __half2float(__low2half(p0a));
            float r1 = v.y - __half2float(__high2half(p0a));
            float r2 = v.z - __half2float(__low2half(p0b));
            float r3 = v.w - __half2float(__high2half(p0b));
            __half2 p1a = __floats2half2_rn(r0, r1);
            __half2 p1b = __floats2half2_rn(r2, r3);
            *(__half2*)&g_wp[0][r][k4]     = p0a;
            *(__half2*)&g_wp[0][r][k4 + 2] = p0b;
            *(__half2*)&g_wp[1][r][k4]     = p1a;
            *(__half2*)&g_wp[1][r][k4 + 2] = p1b;
        }
    }
    __syncthreads();
    if (tid == 0) {
        __threadfence();
        unsigned int ticket = atomicAdd(&g_bar, 1u);
        unsigned int target = (ticket / gridDim.x + 1u) * gridDim.x;
        unsigned int v;
        do {
            asm volatile("ld.global.cg.u32 %0, [%1];" : "=r"(v) : "l"(&g_bar));
            if (v < target) __nanosleep(128);
        } while (v < target);
        __threadfence();
#pragma unroll
        for (int s = 0; s < STAGES; s++) {
            mbar_init(sb + s * 16, NPROD);
            mbar_init(sb + s * 16 + 8, NCONS_THREADS);
        }
    }
    __syncthreads();

    float* acc_s = (float*)(smem + OFF_ACC);
    float* su    = (float*)(smem + OFF_SU);
    int*   s_i1  = (int*)  (smem + OFF_I1);
    int*   s_i2  = (int*)  (smem + OFF_I2);
    float* s_p1  = (float*)(smem + OFF_P1);
    float* s_p2  = (float*)(smem + OFF_P2);
    float* s_v2a = (float*)(smem + OFF_V2A);
    int*   s_list= (int*)  (smem + OFF_LIST);
    int*   s_nf  = (int*)  (smem + OFF_NF);
    float ureg[64];

    if (wid >= 4) {
        // ================= PRODUCER (warps 4-5, 64 threads) =================
        const int ptid = tid - NCONS_THREADS;
        float4 av[16];
        for (int c = 0; c < NC; c++) {
            const int s = c & 1;
            const uint32_t aA = sb + SM_RING + s * STAGE_BYTES;
            const uint32_t aB = aA + STAGE_A;
            mbar_wait(sb + s * 16 + 8, ((c >> 1) & 1) ^ 1);

#pragma unroll
            for (int i = 0; i < 16; i++) {
                int q = ptid + i * NPROD;
                int row = q >> 4, kq = q & 15;
                av[i] = *(const float4*)(x + (size_t)(m0 + row) * DDIM + c * KC + kq * 4);
            }
            // B: plane0 full; plane1 only router rows (0-63) -> skip q >= 1536
#pragma unroll
            for (int i = 0; i < 32; i++) {
                int q = ptid + i * NPROD;
                if (q < 1536) {
                    int pl = q >> 10, rem = q & 1023, row = rem >> 3, cg = rem & 7;
                    uint32_t dst = aB + pl * B_PL + row * RSTRIDE + cg * 16;
                    CPASYNC16(dst, &g_wp[pl][row][c * KC + cg * 8]);
                }
            }
            asm volatile("cp.async.commit_group;" ::: "memory");

#pragma unroll
            for (int i = 0; i < 16; i++) {
                int q = ptid + i * NPROD;
                int row = q >> 4, kq = q & 15;
                uint32_t p0a, p1a, p0b, p1b;
                split2(av[i].x, av[i].y, p0a, p1a);
                split2(av[i].z, av[i].w, p0b, p1b);
                uint32_t base = (aA - sb) + row * RSTRIDE + kq * 8;
                *(uint2*)(smem + base + 0 * A_PL) = make_uint2(p0a, p0b);
                *(uint2*)(smem + base + 1 * A_PL) = make_uint2(p1a, p1b);
            }
            asm volatile("cp.async.wait_group 0;" ::: "memory");
            mbar_arrive(sb + s * 16);
        }
        // u prefetch (hidden under consumer MMA tail)
        {
            const float* ur = u + (size_t)(m0 + ptid) * NEXP;
#pragma unroll
            for (int e = 0; e < 16; e++)
                *(float4*)&ureg[e * 4] = *(const float4*)(ur + e * 4);
        }
        __syncthreads();   // join
        {
            float* srow = su + ptid * US;
#pragma unroll
            for (int e = 0; e < 64; e++) srow[e] = ureg[e];
        }
    } else {
        // ===== CONSUMER (warps 0-3): warp w = rows w*16..w*16+15, all 128 cols =====
        const int w = wid;
        uint32_t aoff = (uint32_t)((w * 16 + (lane & 7) + 8 * ((lane >> 3) & 1)) * RSTRIDE
                                   + 16 * ((lane >> 4) & 1));
        uint32_t boff[8];
#pragma unroll
        for (int ntp = 0; ntp < 8; ntp++) {
            int row = ntp * 16 + ((lane >> 4) & 1) * 8 + (lane & 7);
            boff[ntp] = (uint32_t)(row * RSTRIDE + 16 * ((lane >> 3) & 1));
        }

        float acc[16][4];
#pragma unroll
        for (int nt = 0; nt < 16; nt++)
#pragma unroll
            for (int e = 0; e < 4; e++) acc[nt][e] = 0.f;

        for (int c = 0; c < NC; c++) {
            const int s = c & 1;
            const uint32_t aA = sb + SM_RING + s * STAGE_BYTES;
            const uint32_t aB = aA + STAGE_A;
            mbar_wait(sb + s * 16, (c >> 1) & 1);

#pragma unroll
            for (int ks = 0; ks < 4; ks++) {
                uint32_t a0[4], a1[4], b0[16][2], b1[8][2];
                LDSM4(a0, aA + 0 * A_PL + ks * 32 + aoff);
                LDSM4(a1, aA + 1 * A_PL + ks * 32 + aoff);
#pragma unroll
                for (int ntp = 0; ntp < 8; ntp++) {
                    uint32_t t4[4];
                    LDSM4(t4, aB + 0 * B_PL + ks * 32 + boff[ntp]);
                    b0[2 * ntp][0] = t4[0]; b0[2 * ntp][1] = t4[1];
                    b0[2 * ntp + 1][0] = t4[2]; b0[2 * ntp + 1][1] = t4[3];
                }
                // q00: all 128 cols
#pragma unroll
                for (int nt = 0; nt < 16; nt++)
                    MMA16816(acc[nt], a0, b0[nt]);
                // plane1 B: router cols only
#pragma unroll
                for (int ntp = 0; ntp < 4; ntp++) {
                    uint32_t t4[4];
                    LDSM4(t4, aB + 1 * B_PL + ks * 32 + boff[ntp]);
                    b1[2 * ntp][0] = t4[0]; b1[2 * ntp][1] = t4[1];
                    b1[2 * ntp + 1][0] = t4[2]; b1[2 * ntp + 1][1] = t4[3];
                }
                // q10: x1*w0 router
#pragma unroll
                for (int nt = 0; nt < 8; nt++)
                    MMA16816(acc[nt], a1, b0[nt]);
                // q01: x0*w1 router
#pragma unroll
                for (int nt = 0; nt < 8; nt++)
                    MMA16816(acc[nt], a0, b1[nt]);
            }
            mbar_arrive(sb + s * 16 + 8);
        }

        __syncthreads();   // join
        if (tid == 0) *s_nf = 0;
#pragma unroll
        for (int nt = 0; nt < 16; nt++) {
            int r   = w * 16 + (lane >> 2);
            int col = nt * 8 + (lane & 3) * 2;
            acc_s[r * AS + col]           = acc[nt][0];
            acc_s[r * AS + col + 1]       = acc[nt][1];
            acc_s[(r + 8) * AS + col]     = acc[nt][2];
            acc_s[(r + 8) * AS + col + 1] = acc[nt][3];
        }
    }
    __syncthreads();   // acc_s, su(=u), s_nf ready

    // ---- epilogue step 1: approx noisy values, top-3, flag ----
    if (tid < TM) {
        float* row = acc_s + tid * AS;
        float* nvr = su + tid * US;    // holds u, becomes nv

        float v1 = -INFINITY, v2 = -INFINITY, v3 = -INFINITY;
        int i1 = 0, i2 = 0;
        for (int e = 0; e < NEXP; e++) {
            float lg = row[e] * INVSCALE + rb[e];
            float nz = row[NEXP + e] * INVSCALE + nb[e];
            float sp = fmaxf(nz, 0.f) + log1pf(expf(-fabsf(nz)));
            float nv = lg + sp * nvr[e];
            nvr[e] = nv;
            if (nv > v1)      { v3 = v2; v2 = v1; i2 = i1; v1 = nv; i1 = e; }
            else if (nv > v2) { v3 = v2; v2 = nv; i2 = e; }
            else if (nv > v3) { v3 = nv; }
        }
        float e2 = expf(v2 - v1);
        float den = 1.f + e2;
        s_i1[tid] = i1; s_i2[tid] = i2;
        s_p1[tid] = 1.f / den; s_p2[tid] = e2 / den;
        s_v2a[tid] = v2;
        if ((v1 - v2 < TAU) || (v2 - v3 < TAU)) {
            int pos = atomicAdd(s_nf, 1);
            s_list[pos] = tid;
        }
    }
    __syncthreads();

    // ---- epilogue step 2: exact fix for flagged tokens (1 warp per token) ----
    {
        const int nf = *s_nf;
        float* sx = (float*)(smem + OFF_SX) + wid * DDIM;
        for (int f = wid; f < nf; f += 6) {
            const int t = s_list[f];
            const int m = m0 + t;
            const float* nvr = su + t * US;
            const float cut = s_v2a[t] - TAU;

            // cache x row in this warp's sx buffer
            for (int k4 = lane * 4; k4 < DDIM; k4 += 128)
                *(float4*)(sx + k4) = *(const float4*)(x + (size_t)m * DDIM + k4);
            __syncwarp();

            unsigned mk0 = __ballot_sync(0xffffffffu, nvr[lane] >= cut);
            unsigned mk1 = __ballot_sync(0xffffffffu, nvr[lane + 32] >= cut);

            float v1 = -INFINITY, v2 = -INFINITY;
            int i1 = 0, i2 = 0;
            for (int half = 0; half < 2; half++) {
                unsigned mk = half ? mk1 : mk0;
                while (mk) {
                    int e = __ffs(mk) - 1 + half * 32;
                    mk &= mk - 1;
                    // exact fp32 noise dot product, warp-parallel
                    const float* wrow = nw + (size_t)e * DDIM;
                    float s0 = 0.f, s1 = 0.f, s2 = 0.f, s3 = 0.f;
                    for (int k4 = lane * 4; k4 < DDIM; k4 += 128) {
                        float4 xv = *(const float4*)(sx + k4);
                        float4 wv = *(const float4*)(wrow + k4);
                        s0 += xv.x * wv.x; s1 += xv.y * wv.y;
                        s2 += xv.z * wv.z; s3 += xv.w * wv.w;
                    }
                    float sum = (s0 + s1) + (s2 + s3);
#pragma unroll
                    for (int o = 16; o > 0; o >>= 1)
                        sum += __shfl_xor_sync(0xffffffffu, sum, o);
                    float nz = sum + nb[e];
                    float sp = fmaxf(nz, 0.f) + log1pf(expf(-fabsf(nz)));
                    float lg = acc_s[t * AS + e] * INVSCALE + rb[e];
                    float uu = u[(size_t)m * NEXP + e];
                    float nv = lg + sp * uu;
                    if (lane == 0) {
                        if (nv > v1)      { v2 = v1; i2 = i1; v1 = nv; i1 = e; }
                        else if (nv > v2) { v2 = nv; i2 = e; }
                    }
                }
            }
            if (lane == 0) {
                float e2 = expf(v2 - v1);
                float den = 1.f + e2;
                s_i1[t] = i1; s_i2[t] = i2;
                s_p1[t] = 1.f / den; s_p2[t] = e2 / den;
            }
        }
    }
    __syncthreads();

    // ---- epilogue step 3: build output rows in smem + indices ----
    if (tid < TM) {
        float* row = acc_s + tid * AS;
        for (int e = 0; e < NEXP; e++) row[e] = 0.f;
        row[s_i1[tid]] = s_p1[tid];
        row[s_i2[tid]] = s_p2[tid];
        float* oid = out + (size_t)M * NEXP;
        oid[(size_t)(m0 + tid) * 2 + 0] = (float)s_i1[tid];
        oid[(size_t)(m0 + tid) * 2 + 1] = (float)s_i2[tid];
    }
    __syncthreads();

    // coalesced probability writeback
    for (int t = tid; t < TM * (NEXP / 4); t += NTHREADS) {
        int r = t >> 4;
        int c4 = (t & 15) * 4;
        float4 v = make_float4(acc_s[r * AS + c4 + 0],
                               acc_s[r * AS + c4 + 1],
                               acc_s[r * AS + c4 + 2],
                               acc_s[r * AS + c4 + 3]);
        *(float4*)(out + (size_t)(m0 + r) * NEXP + c4) = v;
    }
}

extern "C" void kernel_launch(void* const* d_in, const int* in_sizes, int n_in,
                              void* d_out, int out_size)
{
    const float* x  = (const float*)d_in[0];
    const float* rw = (const float*)d_in[1];
    const float* rb = (const float*)d_in[2];
    const float* nw = (const float*)d_in[3];
    const float* nb = (const float*)d_in[4];
    const float* u  = (const float*)d_in[5];

    const int M = in_sizes[0] / DDIM;  // 16384

    static bool attr_set = false;
    if (!attr_set) {
        cudaFuncSetAttribute(router_hmma_kernel,
                             cudaFuncAttributeMaxDynamicSharedMemorySize,
                             SMEM_BYTES);
        attr_set = true;
    }

    router_hmma_kernel<<<M / TM, NTHREADS, SMEM_BYTES>>>(x, rw, rb, nw, nb, u,
                                                         (float*)d_out, M);
}

// round 17
// speedup vs baseline: 3.5606x; 1.1550x over previous
#include <cuda_runtime.h>
#include <cuda_fp16.h>
#include <math.h>
#include <stdint.h>

#define DDIM   2048
#define NEXP   64
#define NCOL   128            // router(64) | noise(64) output columns
#define TM     64             // tokens per CTA
#define KC     64             // K elems per chunk
#define NC     (DDIM / KC)    // 32 chunks
#define NTHREADS 192          // 4 consumer warps + 2 producer warps
#define NPROD  64
#define NCONS_THREADS 128
#define AS     133
#define US     65
#define WSCALE 2048.0f
#define INVSCALE (1.0f / 2048.0f)
#define TAU    4e-3f          // flag margin >= 2 * (combined nv error bound)

#define RSTRIDE 144                    // smem row stride bytes (128B data + 16B pad)
#define A_PL    (TM  * RSTRIDE)        // 9216  (single x0 plane)
#define B_PL    (NCOL * RSTRIDE)       // 18432 (single w0 plane)
#define STAGE_BYTES (A_PL + B_PL)      // 27648
#define STAGES  3
#define SM_RING 1024
// ring end = 1024 + 3*27648 = 83968

// epilogue smem layout (overlaps dead ring)
#define OFF_ACC   SM_RING                       // [64][133] f32 -> 34048 B
#define OFF_SU    (OFF_ACC + TM * AS * 4)       // [64][65]  f32 -> 16640 B
#define OFF_I1    (OFF_SU + TM * US * 4)
#define OFF_I2    (OFF_I1 + 256)
#define OFF_P1    (OFF_I2 + 256)
#define OFF_P2    (OFF_P1 + 256)
#define OFF_V2A   (OFF_P2 + 256)
#define OFF_LIST  (OFF_V2A + 256)
#define OFF_NF    (OFF_LIST + 256)
#define OFF_SX    (OFF_NF + 16)                 // 6 warps x 2048 f32 = 49152 B
#define SMEM_EPI  (OFF_SX + 6 * DDIM * 4)       // 102416
#define SMEM_BYTES 102656                       // max(ring 83968, epi 102416), x2 CTAs/SM

// pre-quantized W plane0, scaled by 2048 (router rows 0..63, noise rows 64..127)
__device__ __half g_wp[NCOL][DDIM];
__device__ unsigned int g_bar;   // monotonic epoch ticket barrier (replay-safe)

// ---------------- helpers ----------------
__device__ __forceinline__ uint32_t smem_u32(const void* p) {
    uint32_t a;
    asm("{ .reg .u64 t; cvta.to.shared.u64 t, %1; cvt.u32.u64 %0, t; }" : "=r"(a) : "l"(p));
    return a;
}
__device__ __forceinline__ void mbar_init(uint32_t a, uint32_t cnt) {
    asm volatile("mbarrier.init.shared.b64 [%0], %1;" :: "r"(a), "r"(cnt) : "memory");
}
__device__ __forceinline__ void mbar_arrive(uint32_t a) {
    asm volatile("mbarrier.arrive.shared.b64 _, [%0];" :: "r"(a) : "memory");
}
__device__ __forceinline__ void mbar_wait(uint32_t a, uint32_t parity) {
    asm volatile(
        "{\n\t.reg .pred P1;\n\t"
        "W%=:\n\t"
        "mbarrier.try_wait.parity.acquire.cta.shared::cta.b64 P1, [%0], %1, 0x989680;\n\t"
        "@P1 bra.uni D%=;\n\t"
        "bra.uni W%=;\n\t"
        "D%=:\n\t}"
        :: "r"(a), "r"(parity) : "memory");
}
__device__ __forceinline__ uint32_t pack2h(float lo, float hi) {
    __half2 h = __floats2half2_rn(lo, hi);
    return *reinterpret_cast<uint32_t*>(&h);
}
#define LDSM4(r, a) \
    asm volatile("ldmatrix.sync.aligned.m8n8.x4.shared.b16 {%0,%1,%2,%3}, [%4];" \
        : "=r"((r)[0]), "=r"((r)[1]), "=r"((r)[2]), "=r"((r)[3]) : "r"(a))
#define MMA16816(d, a, b) \
    asm volatile("mma.sync.aligned.m16n8k16.row.col.f32.f16.f16.f32 " \
        "{%0,%1,%2,%3}, {%4,%5,%6,%7}, {%8,%9}, {%0,%1,%2,%3};" \
        : "+f"((d)[0]), "+f"((d)[1]), "+f"((d)[2]), "+f"((d)[3]) \
        : "r"((a)[0]), "r"((a)[1]), "r"((a)[2]), "r"((a)[3]), "r"((b)[0]), "r"((b)[1]))
#define CPASYNC16(dst, src) \
    asm volatile("cp.async.cg.shared.global [%0], [%1], 16;" :: "r"(dst), "l"(src) : "memory")

// ---------------- main fused kernel (single launch) ----------------
extern __shared__ char smem[];

__global__ __launch_bounds__(NTHREADS, 2)
void router_hmma_kernel(const float* __restrict__ x,
                        const float* __restrict__ rw,
                        const float* __restrict__ rb,
                        const float* __restrict__ nw,
                        const float* __restrict__ nb,
                        const float* __restrict__ u,
                        float* __restrict__ out,
                        int M)
{
    const int tid  = threadIdx.x;
    const int wid  = tid >> 5;
    const int lane = tid & 31;
    const int m0   = blockIdx.x * TM;
    const uint32_t sb = smem_u32(smem);

    // ======== inline W prep: quantize this CTA's 1/gridDim slice ========
    {
        const int base = blockIdx.x * 256;
        for (int q = tid; q < 256; q += NTHREADS) {
            int idx = base + q;              // 0 .. 65535 float4 cells
            int r  = idx >> 9;               // row 0..127
            int k4 = (idx & 511) * 4;
            const float* src = (r < NEXP) ? (rw + (size_t)r * DDIM)
                                          : (nw + (size_t)(r - NEXP) * DDIM);
            float4 v = *(const float4*)(src + k4);
            *(uint32_t*)&g_wp[r][k4]     = pack2h(v.x * WSCALE, v.y * WSCALE);
            *(uint32_t*)&g_wp[r][k4 + 2] = pack2h(v.z * WSCALE, v.w * WSCALE);
        }
    }
    __syncthreads();
    if (tid == 0) {
        __threadfence();
        unsigned int ticket = atomicAdd(&g_bar, 1u);
        unsigned int target = (ticket / gridDim.x + 1u) * gridDim.x;
        unsigned int v;
        do {
            asm volatile("ld.global.cg.u32 %0, [%1];" : "=r"(v) : "l"(&g_bar));
            if (v < target) __nanosleep(128);
        } while (v < target);
        __threadfence();
#pragma unroll
        for (int s = 0; s < STAGES; s++) {
            mbar_init(sb + s * 16, NPROD);
            mbar_init(sb + s * 16 + 8, NCONS_THREADS);
        }
    }
    __syncthreads();

    float* acc_s = (float*)(smem + OFF_ACC);
    float* su    = (float*)(smem + OFF_SU);
    int*   s_i1  = (int*)  (smem + OFF_I1);
    int*   s_i2  = (int*)  (smem + OFF_I2);
    float* s_p1  = (float*)(smem + OFF_P1);
    float* s_p2  = (float*)(smem + OFF_P2);
    float* s_v2a = (float*)(smem + OFF_V2A);
    int*   s_list= (int*)  (smem + OFF_LIST);
    int*   s_nf  = (int*)  (smem + OFF_NF);
    float ureg[64];

    if (wid >= 4) {
        // ================= PRODUCER (warps 4-5, 64 threads) =================
        const int ptid = tid - NCONS_THREADS;
        float4 av[16];
        for (int c = 0; c < NC; c++) {
            const int s = c % STAGES;
            const uint32_t aA = sb + SM_RING + s * STAGE_BYTES;
            const uint32_t aB = aA + A_PL;
            mbar_wait(sb + s * 16 + 8, ((c / STAGES) & 1) ^ 1);   // wait empty

            // A: 64 rows x 16 float4, all LDGs upfront
#pragma unroll
            for (int i = 0; i < 16; i++) {
                int q = ptid + i * NPROD;
                int row = q >> 4, kq = q & 15;
                av[i] = *(const float4*)(x + (size_t)(m0 + row) * DDIM + c * KC + kq * 4);
            }
            // B: 1 plane x 128 rows x 8 16B-cells = 1024 cells, 16/thread
#pragma unroll
            for (int i = 0; i < 16; i++) {
                int q = ptid + i * NPROD;
                int row = q >> 3, cg = q & 7;
                uint32_t dst = aB + row * RSTRIDE + cg * 16;
                CPASYNC16(dst, &g_wp[row][c * KC + cg * 8]);
            }
            asm volatile("cp.async.commit_group;" ::: "memory");

            // A cvt + STS (single plane)
#pragma unroll
            for (int i = 0; i < 16; i++) {
                int q = ptid + i * NPROD;
                int row = q >> 4, kq = q & 15;
                uint32_t h0 = pack2h(av[i].x, av[i].y);
                uint32_t h1 = pack2h(av[i].z, av[i].w);
                *(uint2*)(smem + (aA - sb) + row * RSTRIDE + kq * 8) = make_uint2(h0, h1);
            }
            asm volatile("cp.async.wait_group 0;" ::: "memory");
            mbar_arrive(sb + s * 16);                              // full
        }
        // u prefetch (hidden under consumer MMA tail)
        {
            const float* ur = u + (size_t)(m0 + ptid) * NEXP;
#pragma unroll
            for (int e = 0; e < 16; e++)
                *(float4*)&ureg[e * 4] = *(const float4*)(ur + e * 4);
        }
        __syncthreads();   // join
        {
            float* srow = su + ptid * US;
#pragma unroll
            for (int e = 0; e < 64; e++) srow[e] = ureg[e];
        }
    } else {
        // ===== CONSUMER (warps 0-3): warp w = rows w*16..w*16+15, all 128 cols =====
        const int w = wid;
        uint32_t aoff = (uint32_t)((w * 16 + (lane & 7) + 8 * ((lane >> 3) & 1)) * RSTRIDE
                                   + 16 * ((lane >> 4) & 1));
        uint32_t boff[8];
#pragma unroll
        for (int ntp = 0; ntp < 8; ntp++) {
            int row = ntp * 16 + ((lane >> 4) & 1) * 8 + (lane & 7);
            boff[ntp] = (uint32_t)(row * RSTRIDE + 16 * ((lane >> 3) & 1));
        }

        float acc[16][4];
#pragma unroll
        for (int nt = 0; nt < 16; nt++)
#pragma unroll
            for (int e = 0; e < 4; e++) acc[nt][e] = 0.f;

        for (int c = 0; c < NC; c++) {
            const int s = c % STAGES;
            const uint32_t aA = sb + SM_RING + s * STAGE_BYTES;
            const uint32_t aB = aA + A_PL;
            mbar_wait(sb + s * 16, (c / STAGES) & 1);              // wait full

#pragma unroll
            for (int ks = 0; ks < 4; ks++) {
                uint32_t a0[4], b0[16][2];
                LDSM4(a0, aA + ks * 32 + aoff);
#pragma unroll
                for (int ntp = 0; ntp < 8; ntp++) {
                    uint32_t t4[4];
                    LDSM4(t4, aB + ks * 32 + boff[ntp]);
                    b0[2 * ntp][0] = t4[0]; b0[2 * ntp][1] = t4[1];
                    b0[2 * ntp + 1][0] = t4[2]; b0[2 * ntp + 1][1] = t4[3];
                }
#pragma unroll
                for (int nt = 0; nt < 16; nt++)
                    MMA16816(acc[nt], a0, b0[nt]);
            }
            mbar_arrive(sb + s * 16 + 8);                          // arrive empty
        }

        __syncthreads();   // join
        if (tid == 0) *s_nf = 0;
#pragma unroll
        for (int nt = 0; nt < 16; nt++) {
            int r   = w * 16 + (lane >> 2);
            int col = nt * 8 + (lane & 3) * 2;
            acc_s[r * AS + col]           = acc[nt][0];
            acc_s[r * AS + col + 1]       = acc[nt][1];
            acc_s[(r + 8) * AS + col]     = acc[nt][2];
            acc_s[(r + 8) * AS + col + 1] = acc[nt][3];
        }
    }
    __syncthreads();   // acc_s, su(=u), s_nf ready

    // ---- epilogue step 1: approx noisy values, top-3, flag ----
    if (tid < TM) {
        float* row = acc_s + tid * AS;
        float* nvr = su + tid * US;    // holds u, becomes nv

        float v1 = -INFINITY, v2 = -INFINITY, v3 = -INFINITY;
        int i1 = 0, i2 = 0;
        for (int e = 0; e < NEXP; e++) {
            float lg = row[e] * INVSCALE + rb[e];
            float nz = row[NEXP + e] * INVSCALE + nb[e];
            float sp = fmaxf(nz, 0.f) + log1pf(expf(-fabsf(nz)));
            float nv = lg + sp * nvr[e];
            nvr[e] = nv;
            if (nv > v1)      { v3 = v2; v2 = v1; i2 = i1; v1 = nv; i1 = e; }
            else if (nv > v2) { v3 = v2; v2 = nv; i2 = e; }
            else if (nv > v3) { v3 = nv; }
        }
        float e2 = expf(v2 - v1);
        float den = 1.f + e2;
        s_i1[tid] = i1; s_i2[tid] = i2;
        s_p1[tid] = 1.f / den; s_p2[tid] = e2 / den;
        s_v2a[tid] = v2;
        if ((v1 - v2 < TAU) || (v2 - v3 < TAU)) {
            int pos = atomicAdd(s_nf, 1);
            s_list[pos] = tid;
        }
    }
    __syncthreads();

    // ---- epilogue step 2: exact fix (BOTH dots) for flagged tokens ----
    {
        const int nf = *s_nf;
        float* sx = (float*)(smem + OFF_SX) + wid * DDIM;
        for (int f = wid; f < nf; f += 6) {
            const int t = s_list[f];
            const int m = m0 + t;
            const float* nvr = su + t * US;
            const float cut = s_v2a[t] - TAU;

            for (int k4 = lane * 4; k4 < DDIM; k4 += 128)
                *(float4*)(sx + k4) = *(const float4*)(x + (size_t)m * DDIM + k4);
            __syncwarp();

            unsigned mk0 = __ballot_sync(0xffffffffu, nvr[lane] >= cut);
            unsigned mk1 = __ballot_sync(0xffffffffu, nvr[lane + 32] >= cut);

            float v1 = -INFINITY, v2 = -INFINITY;
            int i1 = 0, i2 = 0;
            for (int half = 0; half < 2; half++) {
                unsigned mk = half ? mk1 : mk0;
                while (mk) {
                    int e = __ffs(mk) - 1 + half * 32;
                    mk &= mk - 1;
                    const float* wr = rw + (size_t)e * DDIM;
                    const float* wn = nw + (size_t)e * DDIM;
                    float rs = 0.f, ns = 0.f;
                    for (int k4 = lane * 4; k4 < DDIM; k4 += 128) {
                        float4 xv = *(const float4*)(sx + k4);
                        float4 rv = *(const float4*)(wr + k4);
                        float4 nv4 = *(const float4*)(wn + k4);
                        rs += xv.x * rv.x + xv.y * rv.y + xv.z * rv.z + xv.w * rv.w;
                        ns += xv.x * nv4.x + xv.y * nv4.y + xv.z * nv4.z + xv.w * nv4.w;
                    }
#pragma unroll
                    for (int o = 16; o > 0; o >>= 1) {
                        rs += __shfl_xor_sync(0xffffffffu, rs, o);
                        ns += __shfl_xor_sync(0xffffffffu, ns, o);
                    }
                    float lg = rs + rb[e];
                    float nz = ns + nb[e];
                    float sp = fmaxf(nz, 0.f) + log1pf(expf(-fabsf(nz)));
                    float uu = u[(size_t)m * NEXP + e];
                    float nv = lg + sp * uu;
                    if (lane == 0) {
                        if (nv > v1)      { v2 = v1; i2 = i1; v1 = nv; i1 = e; }
                        else if (nv > v2) { v2 = nv; i2 = e; }
                    }
                }
            }
            if (lane == 0) {
                float e2 = expf(v2 - v1);
                float den = 1.f + e2;
                s_i1[t] = i1; s_i2[t] = i2;
                s_p1[t] = 1.f / den; s_p2[t] = e2 / den;
            }
        }
    }
    __syncthreads();

    // ---- epilogue step 3: build output rows + indices ----
    if (tid < TM) {
        float* row = acc_s + tid * AS;
        for (int e = 0; e < NEXP; e++) row[e] = 0.f;
        row[s_i1[tid]] = s_p1[tid];
        row[s_i2[tid]] = s_p2[tid];
        float* oid = out + (size_t)M * NEXP;
        oid[(size_t)(m0 + tid) * 2 + 0] = (float)s_i1[tid];
        oid[(size_t)(m0 + tid) * 2 + 1] = (float)s_i2[tid];
    }
    __syncthreads();

    // coalesced probability writeback
    for (int t = tid; t < TM * (NEXP / 4); t += NTHREADS) {
        int r = t >> 4;
        int c4 = (t & 15) * 4;
        float4 v = make_float4(acc_s[r * AS + c4 + 0],
                               acc_s[r * AS + c4 + 1],
                               acc_s[r * AS + c4 + 2],
                               acc_s[r * AS + c4 + 3]);
        *(float4*)(out + (size_t)(m0 + r) * NEXP + c4) = v;
    }
}

extern "C" void kernel_launch(void* const* d_in, const int* in_sizes, int n_in,
                              void* d_out, int out_size)
{
    const float* x  = (const float*)d_in[0];
    const float* rw = (const float*)d_in[1];
    const float* rb = (const float*)d_in[2];
    const float* nw = (const float*)d_in[3];
    const float* nb = (const float*)d_in[4];
    const float* u  = (const float*)d_in[5];

    const int M = in_sizes[0] / DDIM;  // 16384

    static bool attr_set = false;
    if (!attr_set) {
        cudaFuncSetAttribute(router_hmma_kernel,
                             cudaFuncAttributeMaxDynamicSharedMemorySize,
                             SMEM_BYTES);
        attr_set = true;
    }

    router_hmma_kernel<<<M / TM, NTHREADS, SMEM_BYTES>>>(x, rw, rb, nw, nb, u,
                                                         (float*)d_out, M);
}